// round 13
// baseline (speedup 1.0000x reference)
#include <cuda_runtime.h>
#include <cuda_bf16.h>
#include <cuda_fp16.h>
#include <math.h>
#include <float.h>
#include <stdint.h>

// Problem constants
#define B_     16
#define C_     384
#define HEADS_ 6
#define D_     64
#define N_     1024
#define O3C    1152
#define C2     (C_ / 2)      // 192

__device__ float g_qkv[B_ * O3C * N_];   // fp32 GEMM outputs
__device__ int g_mask_mode;              // 0 = uint8 bool, 1 = int32, 2 = float32
#define MWORDS (B_ * HEADS_ * N_ * (N_ / 32))
__device__ uint32_t g_mbits[MWORDS];     // bit-packed drop mask

// Pre-split W: hi/lo bf16 k-pairs, [o][c2]
__device__ uint32_t g_wh[O3C * C2];
__device__ uint32_t g_wl[O3C * C2];

// fp16-packed K and V for attention, chunk-major:
// g_kh[(bh*16+kc)*2048 + j*64 + m] = half2(K[2j][64kc+m], K[2j+1][64kc+m])
// g_vh[(bh*16+kc)*2048 + j*64 + d] = half2(V[d][64kc+2j], V[d][64kc+2j+1])
#define KHWORDS (B_ * HEADS_ * 16 * 2048)   // 3,145,728
__device__ uint32_t g_kh[KHWORDS];
__device__ uint32_t g_vh[KHWORDS];

// ---------------------------------------------------------------------------
__device__ __forceinline__ uint32_t pack_f16(float a, float b) {
    __half2 t = __floats2half2_rn(a, b);
    return *(uint32_t*)&t;
}

__device__ __forceinline__ uint32_t pack_bf16(float f0, float f1) {
    __nv_bfloat162 t = __floats2bfloat162_rn(f0, f1);
    return *(uint32_t*)&t;
}

// fp16 m16n8k16 row.col mma, f32 acc in-place
__device__ __forceinline__ void mma16f(float* c, const uint32_t* a,
                                       uint32_t b0, uint32_t b1) {
    asm volatile(
        "mma.sync.aligned.m16n8k16.row.col.f32.f16.f16.f32 "
        "{%0,%1,%2,%3}, {%4,%5,%6,%7}, {%8,%9}, {%0,%1,%2,%3};\n"
        : "+f"(c[0]), "+f"(c[1]), "+f"(c[2]), "+f"(c[3])
        : "r"(a[0]), "r"(a[1]), "r"(a[2]), "r"(a[3]), "r"(b0), "r"(b1));
}

// bf16 m16n8k16 row.col mma, f32 acc in-place (QKV GEMM)
__device__ __forceinline__ void mma16(float* c, const uint32_t* a,
                                      uint32_t b0, uint32_t b1) {
    asm volatile(
        "mma.sync.aligned.m16n8k16.row.col.f32.bf16.bf16.f32 "
        "{%0,%1,%2,%3}, {%4,%5,%6,%7}, {%8,%9}, {%0,%1,%2,%3};\n"
        : "+f"(c[0]), "+f"(c[1]), "+f"(c[2]), "+f"(c[3])
        : "r"(a[0]), "r"(a[1]), "r"(a[2]), "r"(a[3]), "r"(b0), "r"(b1));
}

__device__ __forceinline__ void cpa16(void* smem, const void* g) {
    uint32_t s = (uint32_t)__cvta_generic_to_shared(smem);
    asm volatile("cp.async.cg.shared.global [%0], [%1], 16;" :: "r"(s), "l"(g));
}

__device__ __forceinline__ float fexp2(float y) {
    y = fmaxf(y, -126.0f);
    float z = y + 12582912.0f;
    int   n = __float_as_int(z) - 0x4B400000;
    float f = y - (z - 12582912.0f);
    float p = 1.3333558146e-3f;
    p = fmaf(p, f, 9.6181291076e-3f);
    p = fmaf(p, f, 5.5504108665e-2f);
    p = fmaf(p, f, 2.4022650696e-1f);
    p = fmaf(p, f, 6.9314718056e-1f);
    p = fmaf(p, f, 1.0f);
    return __int_as_float(__float_as_int(p) + (n << 23));
}

// ---------------------------------------------------------------------------
__global__ void detect_mask_kernel(const uint4* __restrict__ m) {
    __shared__ int s_off4, s_gt1;
    if (threadIdx.x == 0) { s_off4 = 0; s_gt1 = 0; }
    __syncthreads();
    int off4 = 0, gt1 = 0;
    for (int i = threadIdx.x; i < 4096; i += blockDim.x) {
        uint4 v = m[i];
        unsigned a = v.x | v.y | v.z | v.w;
        if (a & 0xFFFFFF00u) off4 = 1;
        if (a & 0xFEFEFEFEu) gt1  = 1;
    }
    if (off4) atomicOr(&s_off4, 1);
    if (gt1)  atomicOr(&s_gt1, 1);
    __syncthreads();
    if (threadIdx.x == 0) g_mask_mode = s_gt1 ? 2 : (s_off4 ? 0 : 1);
}

// ---------------------------------------------------------------------------
#define B4(t) (((t) | ((t) >> 7) | ((t) >> 14) | ((t) >> 21)) & 0xFu)

__global__ void maskpack_kernel(const unsigned char* __restrict__ m) {
    int w = blockIdx.x * blockDim.x + threadIdx.x;
    if (w >= MWORDS) return;
    int mode = g_mask_mode;
    uint32_t bits = 0;
    if (mode == 0) {
        const uint4* p = (const uint4*)m + w * 2;
        uint4 a = p[0], b = p[1];
        bits  = B4(a.x) | (B4(a.y) << 4) | (B4(a.z) << 8)  | (B4(a.w) << 12)
              | (B4(b.x) << 16) | (B4(b.y) << 20) | (B4(b.z) << 24) | (B4(b.w) << 28);
    } else if (mode == 1) {
        const int4* p = (const int4*)m + w * 8;
        #pragma unroll
        for (int i = 0; i < 8; i++) {
            int4 v = p[i];
            bits |= (uint32_t)((v.x != 0) | ((v.y != 0) << 1) |
                               ((v.z != 0) << 2) | ((v.w != 0) << 3)) << (i * 4);
        }
    } else {
        const float4* p = (const float4*)m + w * 8;
        #pragma unroll
        for (int i = 0; i < 8; i++) {
            float4 v = p[i];
            bits |= (uint32_t)((v.x != 0.f) | ((v.y != 0.f) << 1) |
                               ((v.z != 0.f) << 2) | ((v.w != 0.f) << 3)) << (i * 4);
        }
    }
    g_mbits[w] = bits;
}

// ---------------------------------------------------------------------------
// W split (horizontal k-pairs): g_wh[o][j] = pack(w[o][2j], w[o][2j+1])
// ---------------------------------------------------------------------------
__global__ void wsplit_kernel(const float* __restrict__ w) {
    int idx = blockIdx.x * blockDim.x + threadIdx.x;
    if (idx >= O3C * C2) return;
    float2 v = *(const float2*)&w[idx * 2];
    __nv_bfloat16 h0 = __float2bfloat16(v.x);
    __nv_bfloat16 h1 = __float2bfloat16(v.y);
    g_wh[idx] = ((uint32_t)*(uint16_t*)&h1 << 16) | *(uint16_t*)&h0;
    g_wl[idx] = pack_bf16(v.x - __bfloat162float(h0),
                          v.y - __bfloat162float(h1));
}

// ---------------------------------------------------------------------------
// K fp16 pack (both reads & writes coalesced)
// ---------------------------------------------------------------------------
__global__ void khalf_kernel() {
    int idx = blockIdx.x * blockDim.x + threadIdx.x;
    if (idx >= KHWORDS) return;
    int m  = idx & 63;
    int j  = (idx >> 6) & 31;
    int kc = (idx >> 11) & 15;
    int bh = idx >> 15;
    int h = bh % HEADS_, b = bh / HEADS_;
    const float* kb = g_qkv + b * O3C * N_ + (C_ + h * D_) * N_;
    int key = kc * 64 + m;
    g_kh[idx] = pack_f16(kb[2 * j * N_ + key], kb[(2 * j + 1) * N_ + key]);
}

// ---------------------------------------------------------------------------
// V fp16 pack with smem transpose: out [j=key-pair][d]
// ---------------------------------------------------------------------------
__global__ void vhalf_kernel() {
    __shared__ float Vs[64][65];
    int blk = blockIdx.x;            // bh*16 + kc
    int kc = blk & 15;
    int bh = blk >> 4;
    int h = bh % HEADS_, b = bh / HEADS_;
    const float* vb = g_qkv + b * O3C * N_ + (2 * C_ + h * D_) * N_ + kc * 64;
    int tid = threadIdx.x;
    for (int e = tid; e < 64 * 16; e += 256) {
        int d = e >> 4, c4 = (e & 15) * 4;
        float4 v = *(const float4*)&vb[d * N_ + c4];
        Vs[d][c4] = v.x; Vs[d][c4 + 1] = v.y;
        Vs[d][c4 + 2] = v.z; Vs[d][c4 + 3] = v.w;
    }
    __syncthreads();
    uint32_t* outp = g_vh + blk * 2048;
    for (int e = tid; e < 2048; e += 256) {
        int j = e >> 6, d = e & 63;
        outp[e] = pack_f16(Vs[d][2 * j], Vs[d][2 * j + 1]);
    }
}

// ---------------------------------------------------------------------------
// QKV GEMM (proven R7/R11 version): bf16 hi/lo 3-term, register-prefetched.
// Tile 128(o) x 128(n), KC=16. 8 warps, warp 32x64. grid (8, 9, 16)
// ---------------------------------------------------------------------------
#define WPST 12
#define XPST 136
#define NCHUNK (C_ / 16)

__global__ __launch_bounds__(256, 2) void qkv_gemm_kernel(
    const float* __restrict__ x)
{
    __shared__ uint32_t Whp[128 * WPST], Wlp[128 * WPST];
    __shared__ uint32_t Xhp[8 * XPST],   Xlp[8 * XPST];

    const int b  = blockIdx.z;
    const int o0 = blockIdx.y * 128;
    const int n0 = blockIdx.x * 128;
    const int tid  = threadIdx.x;
    const int wid  = tid >> 5;
    const int lane = tid & 31;
    const int m_base = (wid >> 1) * 32;
    const int n_base = (wid & 1) * 64;
    const int gi = lane >> 2;
    const int ti = lane & 3;

    const float* xb = x + b * C_ * N_;

    const int wo  = tid >> 1;
    const int wk2 = (tid & 1) * 4;
    const int xc2 = tid >> 5;
    const int xn  = (tid & 31) * 4;

    float acc[2][8][4];
    #pragma unroll
    for (int mf = 0; mf < 2; mf++)
        #pragma unroll
        for (int nf = 0; nf < 8; nf++)
            #pragma unroll
            for (int k = 0; k < 4; k++) acc[mf][nf][k] = 0.f;

    const uint32_t* wh_p = &g_wh[(o0 + wo) * C2 + wk2];
    const uint32_t* wl_p = &g_wl[(o0 + wo) * C2 + wk2];
    const float*    x_p  = &xb[(2 * xc2) * N_ + n0 + xn];
    uint4  whv = *(const uint4*)wh_p;
    uint4  wlv = *(const uint4*)wl_p;
    float4 xr0 = *(const float4*)x_p;
    float4 xr1 = *(const float4*)(x_p + N_);

    for (int ci = 0; ci < NCHUNK; ci++) {
        *(uint4*)&Whp[wo * WPST + wk2] = whv;
        *(uint4*)&Wlp[wo * WPST + wk2] = wlv;
        {
            float a0[4] = {xr0.x, xr0.y, xr0.z, xr0.w};
            float a1[4] = {xr1.x, xr1.y, xr1.z, xr1.w};
            uint32_t ph[4], pl[4];
            #pragma unroll
            for (int j = 0; j < 4; j++) {
                __nv_bfloat16 h0 = __float2bfloat16(a0[j]);
                __nv_bfloat16 h1 = __float2bfloat16(a1[j]);
                ph[j] = ((uint32_t)*(uint16_t*)&h1 << 16) | *(uint16_t*)&h0;
                pl[j] = pack_bf16(a0[j] - __bfloat162float(h0),
                                  a1[j] - __bfloat162float(h1));
            }
            *(uint4*)&Xhp[xc2 * XPST + xn] = make_uint4(ph[0], ph[1], ph[2], ph[3]);
            *(uint4*)&Xlp[xc2 * XPST + xn] = make_uint4(pl[0], pl[1], pl[2], pl[3]);
        }
        __syncthreads();

        if (ci + 1 < NCHUNK) {
            wh_p += 8; wl_p += 8; x_p += 16 * N_;
            whv = *(const uint4*)wh_p;
            wlv = *(const uint4*)wl_p;
            xr0 = *(const float4*)x_p;
            xr1 = *(const float4*)(x_p + N_);
        }

        uint32_t ah[2][4], al[2][4];
        #pragma unroll
        for (int mf = 0; mf < 2; mf++) {
            int r = m_base + mf * 16 + gi;
            ah[mf][0] = Whp[r * WPST + ti];
            ah[mf][1] = Whp[(r + 8) * WPST + ti];
            ah[mf][2] = Whp[r * WPST + ti + 4];
            ah[mf][3] = Whp[(r + 8) * WPST + ti + 4];
            al[mf][0] = Wlp[r * WPST + ti];
            al[mf][1] = Wlp[(r + 8) * WPST + ti];
            al[mf][2] = Wlp[r * WPST + ti + 4];
            al[mf][3] = Wlp[(r + 8) * WPST + ti + 4];
        }
        #pragma unroll
        for (int nf = 0; nf < 8; nf++) {
            int col = n_base + nf * 8 + gi;
            uint32_t bh0 = Xhp[ti * XPST + col];
            uint32_t bh1 = Xhp[(ti + 4) * XPST + col];
            uint32_t bl0 = Xlp[ti * XPST + col];
            uint32_t bl1 = Xlp[(ti + 4) * XPST + col];
            #pragma unroll
            for (int mf = 0; mf < 2; mf++) {
                mma16(acc[mf][nf], ah[mf], bh0, bh1);
                mma16(acc[mf][nf], ah[mf], bl0, bl1);
                mma16(acc[mf][nf], al[mf], bh0, bh1);
            }
        }
        __syncthreads();
    }

    float* outb = g_qkv + b * O3C * N_;
    #pragma unroll
    for (int mf = 0; mf < 2; mf++) {
        int r = o0 + m_base + mf * 16 + gi;
        #pragma unroll
        for (int nf = 0; nf < 8; nf++) {
            int nc2 = n0 + n_base + nf * 8 + 2 * ti;
            *(float2*)&outb[r * N_ + nc2]       = make_float2(acc[mf][nf][0], acc[mf][nf][1]);
            *(float2*)&outb[(r + 8) * N_ + nc2] = make_float2(acc[mf][nf][2], acc[mf][nf][3]);
        }
    }
}

// ---------------------------------------------------------------------------
// Fused flash attention, fp16 mma, chunk-pair pipeline (one barrier per 2
// chunks), quad-buffered cp.async fills 2 chunks ahead. 128 q rows, 8 warps.
// grid = (8, 6, 16)
// ---------------------------------------------------------------------------
#define QHST 36
#define KVST 72
#define QH_WORDS (128 * QHST)                // 4608
#define KB_OFF(i) (QH_WORDS + (i) * 2304)
#define VB_OFF(i) (QH_WORDS + (4 + (i)) * 2304)
#define SMEM_WORDS (QH_WORDS + 8 * 2304)     // 23040
#define ATTN_SMEM (SMEM_WORDS * 4)           // 92160 B

__global__ __launch_bounds__(256, 2) void attn_kernel(float* __restrict__ out)
{
    extern __shared__ uint32_t As[];
    uint32_t* Qh = As;                    // [128][QHST] fp16x2 Q pairs

    const int q0 = blockIdx.x * 128;
    const int h  = blockIdx.y;
    const int b  = blockIdx.z;
    const int tid  = threadIdx.x;
    const int wid  = tid >> 5;
    const int lane = tid & 31;
    const int gi = lane >> 2;
    const int ti = lane & 3;
    const int wq = wid * 16;

    const float sc2 = rsqrtf((float)C_) * 1.4426950408889634f;
    const float NEG = -1e30f;

    const float* qb = g_qkv + (b * O3C + h * D_) * N_;
    const int bh16 = (b * HEADS_ + h) * 16;
    const int mbase = (b * HEADS_ + h) * N_ * N_;

    auto fill = [&](int kc) {
        int bi = kc & 3;
        uint32_t* Kb = As + KB_OFF(bi);
        uint32_t* Vb = As + VB_OFF(bi);
        const uint32_t* kg = g_kh + (bh16 + kc) * 2048;
        const uint32_t* vg = g_vh + (bh16 + kc) * 2048;
        #pragma unroll
        for (int i = 0; i < 2; i++) {
            int e = tid + i * 256;           // 0..511
            int j = e >> 4, m4 = (e & 15) * 4;
            cpa16(&Kb[j * KVST + m4], &kg[j * 64 + m4]);
            cpa16(&Vb[j * KVST + m4], &vg[j * 64 + m4]);
        }
        asm volatile("cp.async.commit_group;" ::: "memory");
    };

    fill(0);
    fill(1);

    // ---- Stage Q as fp16 pairs: Qh[q][j] = half2(Q[2j][q], Q[2j+1][q]) ----
    for (int e = tid; e < 32 * 32; e += 256) {
        int j = e >> 5, q4 = (e & 31) * 4;
        float4 va = *(const float4*)&qb[(2 * j) * N_ + q0 + q4];
        float4 vb4 = *(const float4*)&qb[(2 * j + 1) * N_ + q0 + q4];
        Qh[(q4 + 0) * QHST + j] = pack_f16(va.x, vb4.x);
        Qh[(q4 + 1) * QHST + j] = pack_f16(va.y, vb4.y);
        Qh[(q4 + 2) * QHST + j] = pack_f16(va.z, vb4.z);
        Qh[(q4 + 3) * QHST + j] = pack_f16(va.w, vb4.w);
    }
    __syncthreads();

    // ---- Q A-fragments (k16): 4 ks, 4 regs each ----
    uint32_t qa[4][4];
    #pragma unroll
    for (int ks = 0; ks < 4; ks++) {
        int r = wq + gi, c = 8 * ks + ti;
        qa[ks][0] = Qh[r * QHST + c];
        qa[ks][1] = Qh[(r + 8) * QHST + c];
        qa[ks][2] = Qh[r * QHST + c + 4];
        qa[ks][3] = Qh[(r + 8) * QHST + c + 4];
    }
    // Qh read-only hereafter (never reused)

    float oa[8][4];
    #pragma unroll
    for (int nf = 0; nf < 8; nf++)
        #pragma unroll
        for (int k = 0; k < 4; k++) oa[nf][k] = 0.f;
    float m1 = NEG, m2 = NEG, l1 = 0.f, l2 = 0.f;

    const int r1g = q0 + wq + gi;
    const int mrow = (mbase + r1g * N_) >> 5;

    for (int pc = 0; pc < 8; pc++) {
        const int kc = 2 * pc;
        asm volatile("cp.async.wait_group 0;" ::: "memory");
        __syncthreads();   // chunks kc, kc+1 resident; prior pair fully consumed

        // mask bits for BOTH sub-chunks (one uint4 per row)
        uint4 mwa = *(const uint4*)&g_mbits[mrow + 4 * pc];         // row r1g
        uint4 mwc = *(const uint4*)&g_mbits[mrow + 4 * pc + 256];   // row r1g+8

        if (pc + 1 < 8) { fill(kc + 2); fill(kc + 3); }

        #pragma unroll
        for (int sub = 0; sub < 2; sub++) {
            const int bi = (kc + sub) & 3;
            const uint32_t* Kc = As + KB_OFF(bi);
            const uint32_t* Vc = As + VB_OFF(bi);
            const uint32_t ma0 = sub ? mwa.z : mwa.x;
            const uint32_t ma1 = sub ? mwa.w : mwa.y;
            const uint32_t mc0 = sub ? mwc.z : mwc.x;
            const uint32_t mc1 = sub ? mwc.w : mwc.y;

            // ---- S = Q K^T : 32 mma16 ----
            float sa[8][4];
            #pragma unroll
            for (int nf = 0; nf < 8; nf++)
                #pragma unroll
                for (int k = 0; k < 4; k++) sa[nf][k] = 0.f;
            #pragma unroll
            for (int ks = 0; ks < 4; ks++) {
                const uint32_t* kr0 = &Kc[(8 * ks + ti) * KVST + gi];
                const uint32_t* kr1 = &Kc[(8 * ks + ti + 4) * KVST + gi];
                #pragma unroll
                for (int nf = 0; nf < 8; nf++) {
                    mma16f(sa[nf], qa[ks], kr0[nf * 8], kr1[nf * 8]);
                }
            }

            // ---- scale + mask ----
            #pragma unroll
            for (int nf = 0; nf < 8; nf++) {
                uint32_t wa = (nf < 4) ? ma0 : ma1;
                uint32_t wc = (nf < 4) ? mc0 : mc1;
                int sh = (nf & 3) * 8 + 2 * ti;
                sa[nf][0] = ((wa >> sh) & 1)       ? NEG : sa[nf][0] * sc2;
                sa[nf][1] = ((wa >> (sh + 1)) & 1) ? NEG : sa[nf][1] * sc2;
                sa[nf][2] = ((wc >> sh) & 1)       ? NEG : sa[nf][2] * sc2;
                sa[nf][3] = ((wc >> (sh + 1)) & 1) ? NEG : sa[nf][3] * sc2;
            }

            // ---- online softmax; P packed straight into fp16 A-frags ----
            float mx1 = NEG, mx2 = NEG;
            #pragma unroll
            for (int nf = 0; nf < 8; nf++) {
                mx1 = fmaxf(mx1, fmaxf(sa[nf][0], sa[nf][1]));
                mx2 = fmaxf(mx2, fmaxf(sa[nf][2], sa[nf][3]));
            }
            mx1 = fmaxf(mx1, __shfl_xor_sync(0xffffffffu, mx1, 1));
            mx1 = fmaxf(mx1, __shfl_xor_sync(0xffffffffu, mx1, 2));
            mx2 = fmaxf(mx2, __shfl_xor_sync(0xffffffffu, mx2, 1));
            mx2 = fmaxf(mx2, __shfl_xor_sync(0xffffffffu, mx2, 2));
            float mn1 = fmaxf(m1, mx1), mn2 = fmaxf(m2, mx2);
            float corr1 = fexp2(m1 - mn1), corr2 = fexp2(m2 - mn2);

            uint32_t pa[4][4];
            float ls1 = 0.f, ls2 = 0.f;
            #pragma unroll
            for (int nf = 0; nf < 8; nf++) {
                float p00 = fexp2(sa[nf][0] - mn1);
                float p01 = fexp2(sa[nf][1] - mn1);
                float p10 = fexp2(sa[nf][2] - mn2);
                float p11 = fexp2(sa[nf][3] - mn2);
                ls1 += p00 + p01;
                ls2 += p10 + p11;
                int kf = nf >> 1;
                if (nf & 1) {
                    pa[kf][2] = pack_f16(p00, p01);
                    pa[kf][3] = pack_f16(p10, p11);
                } else {
                    pa[kf][0] = pack_f16(p00, p01);
                    pa[kf][1] = pack_f16(p10, p11);
                }
            }
            ls1 += __shfl_xor_sync(0xffffffffu, ls1, 1);
            ls1 += __shfl_xor_sync(0xffffffffu, ls1, 2);
            ls2 += __shfl_xor_sync(0xffffffffu, ls2, 1);
            ls2 += __shfl_xor_sync(0xffffffffu, ls2, 2);
            l1 = l1 * corr1 + ls1;
            l2 = l2 * corr2 + ls2;
            m1 = mn1; m2 = mn2;
            #pragma unroll
            for (int nf = 0; nf < 8; nf++) {
                oa[nf][0] *= corr1; oa[nf][1] *= corr1;
                oa[nf][2] *= corr2; oa[nf][3] *= corr2;
            }

            // ---- O += P V : 32 mma16, P from registers ----
            #pragma unroll
            for (int kf = 0; kf < 4; kf++) {
                const uint32_t* vr0 = &Vc[(8 * kf + ti) * KVST + gi];
                const uint32_t* vr1 = &Vc[(8 * kf + ti + 4) * KVST + gi];
                #pragma unroll
                for (int nf = 0; nf < 8; nf++) {
                    mma16f(oa[nf], pa[kf], vr0[nf * 8], vr1[nf * 8]);
                }
            }
        }
    }
    __syncthreads();

    // ---- normalize + stage to smem [d][q] for coalesced output ----
    float* Od = (float*)(As + KB_OFF(0));   // overlays K/V buffers
    float il1 = 1.0f / l1, il2 = 1.0f / l2;
    #pragma unroll
    for (int nf = 0; nf < 8; nf++) {
        int d0 = nf * 8 + 2 * ti;
        Od[d0 * 132 + wq + gi]           = oa[nf][0] * il1;
        Od[(d0 + 1) * 132 + wq + gi]     = oa[nf][1] * il1;
        Od[d0 * 132 + wq + gi + 8]       = oa[nf][2] * il2;
        Od[(d0 + 1) * 132 + wq + gi + 8] = oa[nf][3] * il2;
    }
    __syncthreads();

    float* ob = out + (b * C_ + h * D_) * N_;
    for (int e = tid; e < 64 * 32; e += 256) {
        int dd = e >> 5, q4 = (e & 31) * 4;
        *(float4*)&ob[dd * N_ + q0 + q4] = *(const float4*)&Od[dd * 132 + q4];
    }
}

// ---------------------------------------------------------------------------
extern "C" void kernel_launch(void* const* d_in, const int* in_sizes, int n_in,
                              void* d_out, int out_size)
{
    const float* x         = (const float*)d_in[0];
    const float* w_qkv     = (const float*)d_in[1];
    const unsigned char* m = (const unsigned char*)d_in[2];
    float* out             = (float*)d_out;

    cudaFuncSetAttribute(attn_kernel,
                         cudaFuncAttributeMaxDynamicSharedMemorySize, ATTN_SMEM);

    detect_mask_kernel<<<1, 1024>>>((const uint4*)m);
    maskpack_kernel<<<MWORDS / 256, 256>>>(m);
    wsplit_kernel<<<(O3C * C2 + 255) / 256, 256>>>(w_qkv);

    dim3 gemm_grid(N_ / 128, O3C / 128, B_);   // (8, 9, 16)
    qkv_gemm_kernel<<<gemm_grid, 256>>>(x);

    khalf_kernel<<<KHWORDS / 256, 256>>>();
    vhalf_kernel<<<B_ * HEADS_ * 16, 256>>>();

    dim3 attn_grid(N_ / 128, HEADS_, B_);      // (8, 6, 16)
    attn_kernel<<<attn_grid, 256, ATTN_SMEM>>>(out);
}

// round 14
// speedup vs baseline: 1.0627x; 1.0627x over previous
#include <cuda_runtime.h>
#include <cuda_bf16.h>
#include <cuda_fp16.h>
#include <math.h>
#include <float.h>
#include <stdint.h>

// Problem constants
#define B_     16
#define C_     384
#define HEADS_ 6
#define D_     64
#define N_     1024
#define O3C    1152
#define C2     (C_ / 2)      // 192

__device__ int g_mask_mode;              // 0 = uint8 bool, 1 = int32, 2 = float32
#define MWORDS (B_ * HEADS_ * N_ * (N_ / 32))
__device__ uint32_t g_mbits[MWORDS];     // bit-packed drop mask

// Pre-split W: hi/lo bf16 k-pairs, [o][c2]
__device__ uint32_t g_wh[O3C * C2];
__device__ uint32_t g_wl[O3C * C2];

// fp16-packed Q/K/V, written directly by the GEMM epilogue:
// g_qh[(bh*32 + j)*1024 + q]   = half2(Q[2j][q],   Q[2j+1][q])     j = d-pair
// g_kh[(bh*32 + j)*1024 + key] = half2(K[2j][key], K[2j+1][key])
// g_vh[(bh*512 + jk)*64 + d]   = half2(V[d][2jk],  V[d][2jk+1])    jk = key-pair
#define QKWORDS (B_ * HEADS_ * 32 * 1024)   // 3,145,728
__device__ uint32_t g_qh[QKWORDS];
__device__ uint32_t g_kh[QKWORDS];
__device__ uint32_t g_vh[QKWORDS];

// ---------------------------------------------------------------------------
__device__ __forceinline__ uint32_t pack_f16(float a, float b) {
    __half2 t = __floats2half2_rn(a, b);
    return *(uint32_t*)&t;
}

__device__ __forceinline__ uint32_t pack_bf16(float f0, float f1) {
    __nv_bfloat162 t = __floats2bfloat162_rn(f0, f1);
    return *(uint32_t*)&t;
}

// fp16 m16n8k16 row.col mma, f32 acc in-place
__device__ __forceinline__ void mma16f(float* c, const uint32_t* a,
                                       uint32_t b0, uint32_t b1) {
    asm volatile(
        "mma.sync.aligned.m16n8k16.row.col.f32.f16.f16.f32 "
        "{%0,%1,%2,%3}, {%4,%5,%6,%7}, {%8,%9}, {%0,%1,%2,%3};\n"
        : "+f"(c[0]), "+f"(c[1]), "+f"(c[2]), "+f"(c[3])
        : "r"(a[0]), "r"(a[1]), "r"(a[2]), "r"(a[3]), "r"(b0), "r"(b1));
}

// bf16 m16n8k16 row.col mma, f32 acc in-place (QKV GEMM)
__device__ __forceinline__ void mma16(float* c, const uint32_t* a,
                                      uint32_t b0, uint32_t b1) {
    asm volatile(
        "mma.sync.aligned.m16n8k16.row.col.f32.bf16.bf16.f32 "
        "{%0,%1,%2,%3}, {%4,%5,%6,%7}, {%8,%9}, {%0,%1,%2,%3};\n"
        : "+f"(c[0]), "+f"(c[1]), "+f"(c[2]), "+f"(c[3])
        : "r"(a[0]), "r"(a[1]), "r"(a[2]), "r"(a[3]), "r"(b0), "r"(b1));
}

__device__ __forceinline__ void cpa16(void* smem, const void* g) {
    uint32_t s = (uint32_t)__cvta_generic_to_shared(smem);
    asm volatile("cp.async.cg.shared.global [%0], [%1], 16;" :: "r"(s), "l"(g));
}

__device__ __forceinline__ float fexp2(float y) {
    y = fmaxf(y, -126.0f);
    float z = y + 12582912.0f;
    int   n = __float_as_int(z) - 0x4B400000;
    float f = y - (z - 12582912.0f);
    float p = 1.3333558146e-3f;
    p = fmaf(p, f, 9.6181291076e-3f);
    p = fmaf(p, f, 5.5504108665e-2f);
    p = fmaf(p, f, 2.4022650696e-1f);
    p = fmaf(p, f, 6.9314718056e-1f);
    p = fmaf(p, f, 1.0f);
    return __int_as_float(__float_as_int(p) + (n << 23));
}

// ---------------------------------------------------------------------------
__global__ void detect_mask_kernel(const uint4* __restrict__ m) {
    __shared__ int s_off4, s_gt1;
    if (threadIdx.x == 0) { s_off4 = 0; s_gt1 = 0; }
    __syncthreads();
    int off4 = 0, gt1 = 0;
    for (int i = threadIdx.x; i < 4096; i += blockDim.x) {
        uint4 v = m[i];
        unsigned a = v.x | v.y | v.z | v.w;
        if (a & 0xFFFFFF00u) off4 = 1;
        if (a & 0xFEFEFEFEu) gt1  = 1;
    }
    if (off4) atomicOr(&s_off4, 1);
    if (gt1)  atomicOr(&s_gt1, 1);
    __syncthreads();
    if (threadIdx.x == 0) g_mask_mode = s_gt1 ? 2 : (s_off4 ? 0 : 1);
}

// ---------------------------------------------------------------------------
#define B4(t) (((t) | ((t) >> 7) | ((t) >> 14) | ((t) >> 21)) & 0xFu)

__global__ void maskpack_kernel(const unsigned char* __restrict__ m) {
    int w = blockIdx.x * blockDim.x + threadIdx.x;
    if (w >= MWORDS) return;
    int mode = g_mask_mode;
    uint32_t bits = 0;
    if (mode == 0) {
        const uint4* p = (const uint4*)m + w * 2;
        uint4 a = p[0], b = p[1];
        bits  = B4(a.x) | (B4(a.y) << 4) | (B4(a.z) << 8)  | (B4(a.w) << 12)
              | (B4(b.x) << 16) | (B4(b.y) << 20) | (B4(b.z) << 24) | (B4(b.w) << 28);
    } else if (mode == 1) {
        const int4* p = (const int4*)m + w * 8;
        #pragma unroll
        for (int i = 0; i < 8; i++) {
            int4 v = p[i];
            bits |= (uint32_t)((v.x != 0) | ((v.y != 0) << 1) |
                               ((v.z != 0) << 2) | ((v.w != 0) << 3)) << (i * 4);
        }
    } else {
        const float4* p = (const float4*)m + w * 8;
        #pragma unroll
        for (int i = 0; i < 8; i++) {
            float4 v = p[i];
            bits |= (uint32_t)((v.x != 0.f) | ((v.y != 0.f) << 1) |
                               ((v.z != 0.f) << 2) | ((v.w != 0.f) << 3)) << (i * 4);
        }
    }
    g_mbits[w] = bits;
}

// ---------------------------------------------------------------------------
// W split (horizontal k-pairs): g_wh[o][j] = pack(w[o][2j], w[o][2j+1])
// ---------------------------------------------------------------------------
__global__ void wsplit_kernel(const float* __restrict__ w) {
    int idx = blockIdx.x * blockDim.x + threadIdx.x;
    if (idx >= O3C * C2) return;
    float2 v = *(const float2*)&w[idx * 2];
    __nv_bfloat16 h0 = __float2bfloat16(v.x);
    __nv_bfloat16 h1 = __float2bfloat16(v.y);
    g_wh[idx] = ((uint32_t)*(uint16_t*)&h1 << 16) | *(uint16_t*)&h0;
    g_wl[idx] = pack_bf16(v.x - __bfloat162float(h0),
                          v.y - __bfloat162float(h1));
}

// ---------------------------------------------------------------------------
// QKV GEMM: bf16 hi/lo 3-term, register-prefetched. Epilogue packs outputs
// straight to fp16 Q/K/V arrays (no fp32 intermediate, no separate pack pass).
// Tile 128(o) x 128(n), KC=16. 8 warps, warp 32x64. grid (8, 9, 16)
// ---------------------------------------------------------------------------
#define WPST 12
#define XPST 136
#define NCHUNK (C_ / 16)

__global__ __launch_bounds__(256, 2) void qkv_gemm_kernel(
    const float* __restrict__ x)
{
    __shared__ uint32_t Whp[128 * WPST], Wlp[128 * WPST];
    __shared__ uint32_t Xhp[8 * XPST],   Xlp[8 * XPST];

    const int b  = blockIdx.z;
    const int o0 = blockIdx.y * 128;
    const int n0 = blockIdx.x * 128;
    const int tid  = threadIdx.x;
    const int wid  = tid >> 5;
    const int lane = tid & 31;
    const int m_base = (wid >> 1) * 32;
    const int n_base = (wid & 1) * 64;
    const int gi = lane >> 2;
    const int ti = lane & 3;

    const float* xb = x + b * C_ * N_;

    const int wo  = tid >> 1;
    const int wk2 = (tid & 1) * 4;
    const int xc2 = tid >> 5;
    const int xn  = (tid & 31) * 4;

    float acc[2][8][4];
    #pragma unroll
    for (int mf = 0; mf < 2; mf++)
        #pragma unroll
        for (int nf = 0; nf < 8; nf++)
            #pragma unroll
            for (int k = 0; k < 4; k++) acc[mf][nf][k] = 0.f;

    const uint32_t* wh_p = &g_wh[(o0 + wo) * C2 + wk2];
    const uint32_t* wl_p = &g_wl[(o0 + wo) * C2 + wk2];
    const float*    x_p  = &xb[(2 * xc2) * N_ + n0 + xn];
    uint4  whv = *(const uint4*)wh_p;
    uint4  wlv = *(const uint4*)wl_p;
    float4 xr0 = *(const float4*)x_p;
    float4 xr1 = *(const float4*)(x_p + N_);

    for (int ci = 0; ci < NCHUNK; ci++) {
        *(uint4*)&Whp[wo * WPST + wk2] = whv;
        *(uint4*)&Wlp[wo * WPST + wk2] = wlv;
        {
            float a0[4] = {xr0.x, xr0.y, xr0.z, xr0.w};
            float a1[4] = {xr1.x, xr1.y, xr1.z, xr1.w};
            uint32_t ph[4], pl[4];
            #pragma unroll
            for (int j = 0; j < 4; j++) {
                __nv_bfloat16 h0 = __float2bfloat16(a0[j]);
                __nv_bfloat16 h1 = __float2bfloat16(a1[j]);
                ph[j] = ((uint32_t)*(uint16_t*)&h1 << 16) | *(uint16_t*)&h0;
                pl[j] = pack_bf16(a0[j] - __bfloat162float(h0),
                                  a1[j] - __bfloat162float(h1));
            }
            *(uint4*)&Xhp[xc2 * XPST + xn] = make_uint4(ph[0], ph[1], ph[2], ph[3]);
            *(uint4*)&Xlp[xc2 * XPST + xn] = make_uint4(pl[0], pl[1], pl[2], pl[3]);
        }
        __syncthreads();

        if (ci + 1 < NCHUNK) {
            wh_p += 8; wl_p += 8; x_p += 16 * N_;
            whv = *(const uint4*)wh_p;
            wlv = *(const uint4*)wl_p;
            xr0 = *(const float4*)x_p;
            xr1 = *(const float4*)(x_p + N_);
        }

        uint32_t ah[2][4], al[2][4];
        #pragma unroll
        for (int mf = 0; mf < 2; mf++) {
            int r = m_base + mf * 16 + gi;
            ah[mf][0] = Whp[r * WPST + ti];
            ah[mf][1] = Whp[(r + 8) * WPST + ti];
            ah[mf][2] = Whp[r * WPST + ti + 4];
            ah[mf][3] = Whp[(r + 8) * WPST + ti + 4];
            al[mf][0] = Wlp[r * WPST + ti];
            al[mf][1] = Wlp[(r + 8) * WPST + ti];
            al[mf][2] = Wlp[r * WPST + ti + 4];
            al[mf][3] = Wlp[(r + 8) * WPST + ti + 4];
        }
        #pragma unroll
        for (int nf = 0; nf < 8; nf++) {
            int col = n_base + nf * 8 + gi;
            uint32_t bh0 = Xhp[ti * XPST + col];
            uint32_t bh1 = Xhp[(ti + 4) * XPST + col];
            uint32_t bl0 = Xlp[ti * XPST + col];
            uint32_t bl1 = Xlp[(ti + 4) * XPST + col];
            #pragma unroll
            for (int mf = 0; mf < 2; mf++) {
                mma16(acc[mf][nf], ah[mf], bh0, bh1);
                mma16(acc[mf][nf], ah[mf], bl0, bl1);
                mma16(acc[mf][nf], al[mf], bh0, bh1);
            }
        }
        __syncthreads();
    }

    // ---- Epilogue: pack straight to fp16 Q/K/V ----
    const int type  = o0 / C_;        // 0=Q, 1=K, 2=V (tiles are 128-aligned in 384)
    const int obase = o0 - type * C_; // row base within type

    if (type < 2) {
        // Q or K: half2 pairs over adjacent d-rows (shfl with gi+1 partner)
        uint32_t* dst = (type == 0) ? g_qh : g_kh;
        #pragma unroll
        for (int mf = 0; mf < 2; mf++) {
            int r0 = obase + m_base + mf * 16 + gi;   // 0..383, parity = gi parity
            int bh = b * HEADS_ + (r0 >> 6);
            int d0 = r0 & 63;
            #pragma unroll
            for (int nf = 0; nf < 8; nf++) {
                int q = n0 + n_base + nf * 8 + 2 * ti;
                float a0 = acc[mf][nf][0], a1 = acc[mf][nf][1];
                float c0 = acc[mf][nf][2], c1 = acc[mf][nf][3];
                float b0v = __shfl_down_sync(0xffffffffu, a0, 4);
                float b1v = __shfl_down_sync(0xffffffffu, a1, 4);
                float e0v = __shfl_down_sync(0xffffffffu, c0, 4);
                float e1v = __shfl_down_sync(0xffffffffu, c1, 4);
                if ((gi & 1) == 0) {
                    int j0 = d0 >> 1;            // rows d0, d0+1
                    int j1 = (d0 + 8) >> 1;      // rows d0+8, d0+9
                    *(uint2*)&dst[(bh * 32 + j0) * N_ + q] =
                        make_uint2(pack_f16(a0, b0v), pack_f16(a1, b1v));
                    *(uint2*)&dst[(bh * 32 + j1) * N_ + q] =
                        make_uint2(pack_f16(c0, e0v), pack_f16(c1, e1v));
                }
            }
        }
    } else {
        // V: half2 pairs over adjacent keys (held in-thread, no shfl)
        #pragma unroll
        for (int mf = 0; mf < 2; mf++) {
            int r0 = obase + m_base + mf * 16 + gi;   // d row
            int bh = b * HEADS_ + (r0 >> 6);
            int d0 = r0 & 63;
            #pragma unroll
            for (int nf = 0; nf < 8; nf++) {
                int q = n0 + n_base + nf * 8 + 2 * ti;   // even key
                int jk = q >> 1;
                g_vh[(bh * 512 + jk) * 64 + d0]     = pack_f16(acc[mf][nf][0], acc[mf][nf][1]);
                g_vh[(bh * 512 + jk) * 64 + d0 + 8] = pack_f16(acc[mf][nf][2], acc[mf][nf][3]);
            }
        }
    }
}

// ---------------------------------------------------------------------------
// Fused flash attention (R11 structure), fp16 mma, packed Q/K/V inputs.
// 128 q rows, 8 warps. Double-buffered cp.async K/V. grid = (8, 6, 16)
// ---------------------------------------------------------------------------
#define QST 132
#define KVST 72
#define QH_WORDS (32 * QST)              // 4224
#define K0_OFF QH_WORDS                  // 4224
#define V0_OFF (K0_OFF + 32 * KVST)      // 6528
#define K1_OFF (V0_OFF + 32 * KVST)      // 8832
#define V1_OFF (K1_OFF + 32 * KVST)      // 11136
#define SMEM_WORDS (V1_OFF + 32 * KVST)  // 13440
#define ATTN_SMEM (SMEM_WORDS * 4)       // 53760 B

__global__ __launch_bounds__(256, 2) void attn_kernel(float* __restrict__ out)
{
    extern __shared__ uint32_t As[];
    uint32_t* Qh = As;                    // [32 j][QST] fp16x2 Q pairs

    const int q0 = blockIdx.x * 128;
    const int h  = blockIdx.y;
    const int b  = blockIdx.z;
    const int tid  = threadIdx.x;
    const int wid  = tid >> 5;
    const int lane = tid & 31;
    const int gi = lane >> 2;
    const int ti = lane & 3;
    const int wq = wid * 16;

    const float sc2 = rsqrtf((float)C_) * 1.4426950408889634f;
    const float NEG = -1e30f;

    const int bh = b * HEADS_ + h;
    const uint32_t* qg = g_qh + bh * 32 * N_;
    const int mbase = bh * N_ * N_;

    auto fill = [&](int sel, int kc) {
        uint32_t* Kb = As + (sel ? K1_OFF : K0_OFF);
        uint32_t* Vb = As + (sel ? V1_OFF : V0_OFF);
        const uint32_t* kg = g_kh + bh * 32 * N_ + kc * 64;
        const uint32_t* vg = g_vh + (bh * 512 + kc * 32) * 64;
        #pragma unroll
        for (int i = 0; i < 2; i++) {
            int e = tid + i * 256;           // 0..511
            int j = e >> 4, m4 = (e & 15) * 4;
            cpa16(&Kb[j * KVST + m4], &kg[j * N_ + m4]);
            cpa16(&Vb[j * KVST + m4], &vg[j * 64 + m4]);
        }
        asm volatile("cp.async.commit_group;" ::: "memory");
    };

    fill(0, 0);

    // ---- Stage Q: smem [j][q], raw copy of packed fp16 pairs ----
    for (int e = tid; e < 1024; e += 256) {
        int j = e >> 5, q4 = (e & 31) * 4;
        *(uint4*)&Qh[j * QST + q4] = *(const uint4*)&qg[j * N_ + q0 + q4];
    }
    __syncthreads();

    // ---- Q A-fragments (k16): 4 ks, 4 regs each; banks 4ti+gi (free) ----
    uint32_t qa[4][4];
    #pragma unroll
    for (int ks = 0; ks < 4; ks++) {
        int c = 8 * ks + ti, r = wq + gi;
        qa[ks][0] = Qh[c * QST + r];
        qa[ks][1] = Qh[c * QST + r + 8];
        qa[ks][2] = Qh[(c + 4) * QST + r];
        qa[ks][3] = Qh[(c + 4) * QST + r + 8];
    }
    // Qh read-only hereafter

    float oa[8][4];
    #pragma unroll
    for (int nf = 0; nf < 8; nf++)
        #pragma unroll
        for (int k = 0; k < 4; k++) oa[nf][k] = 0.f;
    float m1 = NEG, m2 = NEG, l1 = 0.f, l2 = 0.f;

    const int r1g = q0 + wq + gi;
    const int mrow = (mbase + r1g * N_) >> 5;

    for (int kc = 0; kc < 16; kc++) {
        asm volatile("cp.async.wait_group 0;" ::: "memory");
        __syncthreads();

        const int widx = mrow + kc * 2;
        uint2 mwa = *(const uint2*)&g_mbits[widx];
        uint2 mwc = *(const uint2*)&g_mbits[widx + 256];

        if (kc + 1 < 16) fill((kc + 1) & 1, kc + 1);

        const uint32_t* Kc = As + ((kc & 1) ? K1_OFF : K0_OFF);
        const uint32_t* Vc = As + ((kc & 1) ? V1_OFF : V0_OFF);

        // ---- S = Q K^T : 32 mma16 ----
        float sa[8][4];
        #pragma unroll
        for (int nf = 0; nf < 8; nf++)
            #pragma unroll
            for (int k = 0; k < 4; k++) sa[nf][k] = 0.f;
        #pragma unroll
        for (int ks = 0; ks < 4; ks++) {
            const uint32_t* kr0 = &Kc[(8 * ks + ti) * KVST + gi];
            const uint32_t* kr1 = &Kc[(8 * ks + ti + 4) * KVST + gi];
            #pragma unroll
            for (int nf = 0; nf < 8; nf++) {
                mma16f(sa[nf], qa[ks], kr0[nf * 8], kr1[nf * 8]);
            }
        }

        // ---- scale + mask ----
        #pragma unroll
        for (int nf = 0; nf < 8; nf++) {
            uint32_t wa = (nf < 4) ? mwa.x : mwa.y;
            uint32_t wc = (nf < 4) ? mwc.x : mwc.y;
            int sh = (nf & 3) * 8 + 2 * ti;
            sa[nf][0] = ((wa >> sh) & 1)       ? NEG : sa[nf][0] * sc2;
            sa[nf][1] = ((wa >> (sh + 1)) & 1) ? NEG : sa[nf][1] * sc2;
            sa[nf][2] = ((wc >> sh) & 1)       ? NEG : sa[nf][2] * sc2;
            sa[nf][3] = ((wc >> (sh + 1)) & 1) ? NEG : sa[nf][3] * sc2;
        }

        // ---- online softmax; P packed straight into fp16 A-frags ----
        float mx1 = NEG, mx2 = NEG;
        #pragma unroll
        for (int nf = 0; nf < 8; nf++) {
            mx1 = fmaxf(mx1, fmaxf(sa[nf][0], sa[nf][1]));
            mx2 = fmaxf(mx2, fmaxf(sa[nf][2], sa[nf][3]));
        }
        mx1 = fmaxf(mx1, __shfl_xor_sync(0xffffffffu, mx1, 1));
        mx1 = fmaxf(mx1, __shfl_xor_sync(0xffffffffu, mx1, 2));
        mx2 = fmaxf(mx2, __shfl_xor_sync(0xffffffffu, mx2, 1));
        mx2 = fmaxf(mx2, __shfl_xor_sync(0xffffffffu, mx2, 2));
        float mn1 = fmaxf(m1, mx1), mn2 = fmaxf(m2, mx2);
        float corr1 = fexp2(m1 - mn1), corr2 = fexp2(m2 - mn2);

        uint32_t pa[4][4];
        float ls1 = 0.f, ls2 = 0.f;
        #pragma unroll
        for (int nf = 0; nf < 8; nf++) {
            float p00 = fexp2(sa[nf][0] - mn1);
            float p01 = fexp2(sa[nf][1] - mn1);
            float p10 = fexp2(sa[nf][2] - mn2);
            float p11 = fexp2(sa[nf][3] - mn2);
            ls1 += p00 + p01;
            ls2 += p10 + p11;
            int kf = nf >> 1;
            if (nf & 1) {
                pa[kf][2] = pack_f16(p00, p01);
                pa[kf][3] = pack_f16(p10, p11);
            } else {
                pa[kf][0] = pack_f16(p00, p01);
                pa[kf][1] = pack_f16(p10, p11);
            }
        }
        ls1 += __shfl_xor_sync(0xffffffffu, ls1, 1);
        ls1 += __shfl_xor_sync(0xffffffffu, ls1, 2);
        ls2 += __shfl_xor_sync(0xffffffffu, ls2, 1);
        ls2 += __shfl_xor_sync(0xffffffffu, ls2, 2);
        l1 = l1 * corr1 + ls1;
        l2 = l2 * corr2 + ls2;
        m1 = mn1; m2 = mn2;
        #pragma unroll
        for (int nf = 0; nf < 8; nf++) {
            oa[nf][0] *= corr1; oa[nf][1] *= corr1;
            oa[nf][2] *= corr2; oa[nf][3] *= corr2;
        }

        // ---- O += P V : 32 mma16, P from registers ----
        #pragma unroll
        for (int kf = 0; kf < 4; kf++) {
            const uint32_t* vr0 = &Vc[(8 * kf + ti) * KVST + gi];
            const uint32_t* vr1 = &Vc[(8 * kf + ti + 4) * KVST + gi];
            #pragma unroll
            for (int nf = 0; nf < 8; nf++) {
                mma16f(oa[nf], pa[kf], vr0[nf * 8], vr1[nf * 8]);
            }
        }
    }
    __syncthreads();

    // ---- normalize + stage to smem [d][q] for coalesced output ----
    float* Od = (float*)(As + K0_OFF);   // [64][132] staging (overlays buffers)
    float il1 = 1.0f / l1, il2 = 1.0f / l2;
    #pragma unroll
    for (int nf = 0; nf < 8; nf++) {
        int d0 = nf * 8 + 2 * ti;
        Od[d0 * 132 + wq + gi]           = oa[nf][0] * il1;
        Od[(d0 + 1) * 132 + wq + gi]     = oa[nf][1] * il1;
        Od[d0 * 132 + wq + gi + 8]       = oa[nf][2] * il2;
        Od[(d0 + 1) * 132 + wq + gi + 8] = oa[nf][3] * il2;
    }
    __syncthreads();

    float* ob = out + (b * C_ + h * D_) * N_;
    for (int e = tid; e < 64 * 32; e += 256) {
        int dd = e >> 5, q4 = (e & 31) * 4;
        *(float4*)&ob[dd * N_ + q0 + q4] = *(const float4*)&Od[dd * 132 + q4];
    }
}

// ---------------------------------------------------------------------------
extern "C" void kernel_launch(void* const* d_in, const int* in_sizes, int n_in,
                              void* d_out, int out_size)
{
    const float* x         = (const float*)d_in[0];
    const float* w_qkv     = (const float*)d_in[1];
    const unsigned char* m = (const unsigned char*)d_in[2];
    float* out             = (float*)d_out;

    cudaFuncSetAttribute(attn_kernel,
                         cudaFuncAttributeMaxDynamicSharedMemorySize, ATTN_SMEM);

    detect_mask_kernel<<<1, 1024>>>((const uint4*)m);
    maskpack_kernel<<<MWORDS / 256, 256>>>(m);
    wsplit_kernel<<<(O3C * C2 + 255) / 256, 256>>>(w_qkv);

    dim3 gemm_grid(N_ / 128, O3C / 128, B_);   // (8, 9, 16)
    qkv_gemm_kernel<<<gemm_grid, 256>>>(x);

    dim3 attn_grid(N_ / 128, HEADS_, B_);      // (8, 6, 16)
    attn_kernel<<<attn_grid, 256, ATTN_SMEM>>>(out);
}

// round 15
// speedup vs baseline: 1.1469x; 1.0792x over previous
#include <cuda_runtime.h>
#include <cuda_bf16.h>
#include <cuda_fp16.h>
#include <math.h>
#include <float.h>
#include <stdint.h>

// Problem constants
#define B_     16
#define C_     384
#define HEADS_ 6
#define D_     64
#define N_     1024
#define O3C    1152
#define C2     (C_ / 2)      // 192

__device__ int g_mask_mode;              // 0 = uint8 bool, 1 = int32, 2 = float32
#define MWORDS (B_ * HEADS_ * N_ * (N_ / 32))
__device__ uint32_t g_mbits[MWORDS];     // bit-packed drop mask

// Pre-split W: fp16 hi/lo k-pairs, [o][c2]  (lo = exact residual, may be subnormal)
__device__ uint32_t g_wh[O3C * C2];
__device__ uint32_t g_wl[O3C * C2];

// fp16-packed Q/K/V, written directly by the GEMM epilogue:
// g_qh[(bh*32 + j)*1024 + q]   = half2(Q[2j][q],   Q[2j+1][q])     j = d-pair
// g_kh[(bh*32 + j)*1024 + key] = half2(K[2j][key], K[2j+1][key])
// g_vh[(bh*512 + jk)*64 + d]   = half2(V[d][2jk],  V[d][2jk+1])    jk = key-pair
#define QKWORDS (B_ * HEADS_ * 32 * 1024)   // 3,145,728
__device__ uint32_t g_qh[QKWORDS];
__device__ uint32_t g_kh[QKWORDS];
__device__ uint32_t g_vh[QKWORDS];

// ---------------------------------------------------------------------------
__device__ __forceinline__ uint32_t pack_f16(float a, float b) {
    __half2 t = __floats2half2_rn(a, b);
    return *(uint32_t*)&t;
}

// fp16 m16n8k16 row.col mma, f32 acc in-place
__device__ __forceinline__ void mma16f(float* c, const uint32_t* a,
                                       uint32_t b0, uint32_t b1) {
    asm volatile(
        "mma.sync.aligned.m16n8k16.row.col.f32.f16.f16.f32 "
        "{%0,%1,%2,%3}, {%4,%5,%6,%7}, {%8,%9}, {%0,%1,%2,%3};\n"
        : "+f"(c[0]), "+f"(c[1]), "+f"(c[2]), "+f"(c[3])
        : "r"(a[0]), "r"(a[1]), "r"(a[2]), "r"(a[3]), "r"(b0), "r"(b1));
}

__device__ __forceinline__ void cpa16(void* smem, const void* g) {
    uint32_t s = (uint32_t)__cvta_generic_to_shared(smem);
    asm volatile("cp.async.cg.shared.global [%0], [%1], 16;" :: "r"(s), "l"(g));
}

__device__ __forceinline__ float fexp2(float y) {
    y = fmaxf(y, -126.0f);
    float z = y + 12582912.0f;
    int   n = __float_as_int(z) - 0x4B400000;
    float f = y - (z - 12582912.0f);
    float p = 1.3333558146e-3f;
    p = fmaf(p, f, 9.6181291076e-3f);
    p = fmaf(p, f, 5.5504108665e-2f);
    p = fmaf(p, f, 2.4022650696e-1f);
    p = fmaf(p, f, 6.9314718056e-1f);
    p = fmaf(p, f, 1.0f);
    return __int_as_float(__float_as_int(p) + (n << 23));
}

// ---------------------------------------------------------------------------
__global__ void detect_mask_kernel(const uint4* __restrict__ m) {
    __shared__ int s_off4, s_gt1;
    if (threadIdx.x == 0) { s_off4 = 0; s_gt1 = 0; }
    __syncthreads();
    int off4 = 0, gt1 = 0;
    for (int i = threadIdx.x; i < 4096; i += blockDim.x) {
        uint4 v = m[i];
        unsigned a = v.x | v.y | v.z | v.w;
        if (a & 0xFFFFFF00u) off4 = 1;
        if (a & 0xFEFEFEFEu) gt1  = 1;
    }
    if (off4) atomicOr(&s_off4, 1);
    if (gt1)  atomicOr(&s_gt1, 1);
    __syncthreads();
    if (threadIdx.x == 0) g_mask_mode = s_gt1 ? 2 : (s_off4 ? 0 : 1);
}

// ---------------------------------------------------------------------------
#define B4(t) (((t) | ((t) >> 7) | ((t) >> 14) | ((t) >> 21)) & 0xFu)

__global__ void maskpack_kernel(const unsigned char* __restrict__ m) {
    int w = blockIdx.x * blockDim.x + threadIdx.x;
    if (w >= MWORDS) return;
    int mode = g_mask_mode;
    uint32_t bits = 0;
    if (mode == 0) {
        const uint4* p = (const uint4*)m + w * 2;
        uint4 a = p[0], b = p[1];
        bits  = B4(a.x) | (B4(a.y) << 4) | (B4(a.z) << 8)  | (B4(a.w) << 12)
              | (B4(b.x) << 16) | (B4(b.y) << 20) | (B4(b.z) << 24) | (B4(b.w) << 28);
    } else if (mode == 1) {
        const int4* p = (const int4*)m + w * 8;
        #pragma unroll
        for (int i = 0; i < 8; i++) {
            int4 v = p[i];
            bits |= (uint32_t)((v.x != 0) | ((v.y != 0) << 1) |
                               ((v.z != 0) << 2) | ((v.w != 0) << 3)) << (i * 4);
        }
    } else {
        const float4* p = (const float4*)m + w * 8;
        #pragma unroll
        for (int i = 0; i < 8; i++) {
            float4 v = p[i];
            bits |= (uint32_t)((v.x != 0.f) | ((v.y != 0.f) << 1) |
                               ((v.z != 0.f) << 2) | ((v.w != 0.f) << 3)) << (i * 4);
        }
    }
    g_mbits[w] = bits;
}

// ---------------------------------------------------------------------------
// W split (fp16 hi/lo, horizontal k-pairs):
// g_wh[o][j] = f16pack(w[o][2j], w[o][2j+1]); g_wl = residuals
// ---------------------------------------------------------------------------
__global__ void wsplit_kernel(const float* __restrict__ w) {
    int idx = blockIdx.x * blockDim.x + threadIdx.x;
    if (idx >= O3C * C2) return;
    float2 v = *(const float2*)&w[idx * 2];
    __half h0 = __float2half_rn(v.x);
    __half h1 = __float2half_rn(v.y);
    __half2 hp; hp.x = h0; hp.y = h1;
    g_wh[idx] = *(uint32_t*)&hp;
    g_wl[idx] = pack_f16(v.x - __half2float(h0),
                         v.y - __half2float(h1));
}

// ---------------------------------------------------------------------------
// QKV GEMM: fp16, W hi/lo 2-term, X single fp16. Register-prefetched chunks.
// Epilogue packs outputs straight to fp16 Q/K/V arrays.
// Tile 128(o) x 128(n), KC=16. 8 warps, warp 32x64. grid (8, 9, 16)
// ---------------------------------------------------------------------------
#define WPST 12
#define XPST 136
#define NCHUNK (C_ / 16)

__global__ __launch_bounds__(256, 2) void qkv_gemm_kernel(
    const float* __restrict__ x)
{
    __shared__ uint32_t Whp[128 * WPST], Wlp[128 * WPST];
    __shared__ uint32_t Xhp[8 * XPST];

    const int b  = blockIdx.z;
    const int o0 = blockIdx.y * 128;
    const int n0 = blockIdx.x * 128;
    const int tid  = threadIdx.x;
    const int wid  = tid >> 5;
    const int lane = tid & 31;
    const int m_base = (wid >> 1) * 32;
    const int n_base = (wid & 1) * 64;
    const int gi = lane >> 2;
    const int ti = lane & 3;

    const float* xb = x + b * C_ * N_;

    const int wo  = tid >> 1;
    const int wk2 = (tid & 1) * 4;
    const int xc2 = tid >> 5;
    const int xn  = (tid & 31) * 4;

    float acc[2][8][4];
    #pragma unroll
    for (int mf = 0; mf < 2; mf++)
        #pragma unroll
        for (int nf = 0; nf < 8; nf++)
            #pragma unroll
            for (int k = 0; k < 4; k++) acc[mf][nf][k] = 0.f;

    const uint32_t* wh_p = &g_wh[(o0 + wo) * C2 + wk2];
    const uint32_t* wl_p = &g_wl[(o0 + wo) * C2 + wk2];
    const float*    x_p  = &xb[(2 * xc2) * N_ + n0 + xn];
    uint4  whv = *(const uint4*)wh_p;
    uint4  wlv = *(const uint4*)wl_p;
    float4 xr0 = *(const float4*)x_p;
    float4 xr1 = *(const float4*)(x_p + N_);

    for (int ci = 0; ci < NCHUNK; ci++) {
        *(uint4*)&Whp[wo * WPST + wk2] = whv;
        *(uint4*)&Wlp[wo * WPST + wk2] = wlv;
        {
            // vertical k-pairs, single fp16 (no lo)
            uint4 hv;
            hv.x = pack_f16(xr0.x, xr1.x);
            hv.y = pack_f16(xr0.y, xr1.y);
            hv.z = pack_f16(xr0.z, xr1.z);
            hv.w = pack_f16(xr0.w, xr1.w);
            *(uint4*)&Xhp[xc2 * XPST + xn] = hv;
        }
        __syncthreads();

        if (ci + 1 < NCHUNK) {
            wh_p += 8; wl_p += 8; x_p += 16 * N_;
            whv = *(const uint4*)wh_p;
            wlv = *(const uint4*)wl_p;
            xr0 = *(const float4*)x_p;
            xr1 = *(const float4*)(x_p + N_);
        }

        uint32_t ah[2][4], al[2][4];
        #pragma unroll
        for (int mf = 0; mf < 2; mf++) {
            int r = m_base + mf * 16 + gi;
            ah[mf][0] = Whp[r * WPST + ti];
            ah[mf][1] = Whp[(r + 8) * WPST + ti];
            ah[mf][2] = Whp[r * WPST + ti + 4];
            ah[mf][3] = Whp[(r + 8) * WPST + ti + 4];
            al[mf][0] = Wlp[r * WPST + ti];
            al[mf][1] = Wlp[(r + 8) * WPST + ti];
            al[mf][2] = Wlp[r * WPST + ti + 4];
            al[mf][3] = Wlp[(r + 8) * WPST + ti + 4];
        }
        #pragma unroll
        for (int nf = 0; nf < 8; nf++) {
            int col = n_base + nf * 8 + gi;
            uint32_t bh0 = Xhp[ti * XPST + col];
            uint32_t bh1 = Xhp[(ti + 4) * XPST + col];
            #pragma unroll
            for (int mf = 0; mf < 2; mf++) {
                mma16f(acc[mf][nf], ah[mf], bh0, bh1);
                mma16f(acc[mf][nf], al[mf], bh0, bh1);
            }
        }
        __syncthreads();
    }

    // ---- Epilogue: pack straight to fp16 Q/K/V ----
    const int type  = o0 / C_;        // 0=Q, 1=K, 2=V
    const int obase = o0 - type * C_;

    if (type < 2) {
        // Q or K: half2 pairs over adjacent d-rows (shfl with gi+1 partner)
        uint32_t* dst = (type == 0) ? g_qh : g_kh;
        #pragma unroll
        for (int mf = 0; mf < 2; mf++) {
            int r0 = obase + m_base + mf * 16 + gi;
            int bh = b * HEADS_ + (r0 >> 6);
            int d0 = r0 & 63;
            #pragma unroll
            for (int nf = 0; nf < 8; nf++) {
                int q = n0 + n_base + nf * 8 + 2 * ti;
                float a0 = acc[mf][nf][0], a1 = acc[mf][nf][1];
                float c0 = acc[mf][nf][2], c1 = acc[mf][nf][3];
                float b0v = __shfl_down_sync(0xffffffffu, a0, 4);
                float b1v = __shfl_down_sync(0xffffffffu, a1, 4);
                float e0v = __shfl_down_sync(0xffffffffu, c0, 4);
                float e1v = __shfl_down_sync(0xffffffffu, c1, 4);
                if ((gi & 1) == 0) {
                    int j0 = d0 >> 1;
                    int j1 = (d0 + 8) >> 1;
                    *(uint2*)&dst[(bh * 32 + j0) * N_ + q] =
                        make_uint2(pack_f16(a0, b0v), pack_f16(a1, b1v));
                    *(uint2*)&dst[(bh * 32 + j1) * N_ + q] =
                        make_uint2(pack_f16(c0, e0v), pack_f16(c1, e1v));
                }
            }
        }
    } else {
        // V: half2 pairs over adjacent keys (held in-thread)
        #pragma unroll
        for (int mf = 0; mf < 2; mf++) {
            int r0 = obase + m_base + mf * 16 + gi;
            int bh = b * HEADS_ + (r0 >> 6);
            int d0 = r0 & 63;
            #pragma unroll
            for (int nf = 0; nf < 8; nf++) {
                int q = n0 + n_base + nf * 8 + 2 * ti;
                int jk = q >> 1;
                g_vh[(bh * 512 + jk) * 64 + d0]     = pack_f16(acc[mf][nf][0], acc[mf][nf][1]);
                g_vh[(bh * 512 + jk) * 64 + d0 + 8] = pack_f16(acc[mf][nf][2], acc[mf][nf][3]);
            }
        }
    }
}

// ---------------------------------------------------------------------------
// Fused flash attention (R14 verbatim): fp16 mma, packed Q/K/V inputs.
// 128 q rows, 8 warps. Double-buffered cp.async K/V. grid = (8, 6, 16)
// ---------------------------------------------------------------------------
#define QST 132
#define KVST 72
#define QH_WORDS (32 * QST)              // 4224
#define K0_OFF QH_WORDS                  // 4224
#define V0_OFF (K0_OFF + 32 * KVST)      // 6528
#define K1_OFF (V0_OFF + 32 * KVST)      // 8832
#define V1_OFF (K1_OFF + 32 * KVST)      // 11136
#define SMEM_WORDS (V1_OFF + 32 * KVST)  // 13440
#define ATTN_SMEM (SMEM_WORDS * 4)       // 53760 B

__global__ __launch_bounds__(256, 2) void attn_kernel(float* __restrict__ out)
{
    extern __shared__ uint32_t As[];
    uint32_t* Qh = As;                    // [32 j][QST] fp16x2 Q pairs

    const int q0 = blockIdx.x * 128;
    const int h  = blockIdx.y;
    const int b  = blockIdx.z;
    const int tid  = threadIdx.x;
    const int wid  = tid >> 5;
    const int lane = tid & 31;
    const int gi = lane >> 2;
    const int ti = lane & 3;
    const int wq = wid * 16;

    const float sc2 = rsqrtf((float)C_) * 1.4426950408889634f;
    const float NEG = -1e30f;

    const int bh = b * HEADS_ + h;
    const uint32_t* qg = g_qh + bh * 32 * N_;
    const int mbase = bh * N_ * N_;

    auto fill = [&](int sel, int kc) {
        uint32_t* Kb = As + (sel ? K1_OFF : K0_OFF);
        uint32_t* Vb = As + (sel ? V1_OFF : V0_OFF);
        const uint32_t* kg = g_kh + bh * 32 * N_ + kc * 64;
        const uint32_t* vg = g_vh + (bh * 512 + kc * 32) * 64;
        #pragma unroll
        for (int i = 0; i < 2; i++) {
            int e = tid + i * 256;           // 0..511
            int j = e >> 4, m4 = (e & 15) * 4;
            cpa16(&Kb[j * KVST + m4], &kg[j * N_ + m4]);
            cpa16(&Vb[j * KVST + m4], &vg[j * 64 + m4]);
        }
        asm volatile("cp.async.commit_group;" ::: "memory");
    };

    fill(0, 0);

    // ---- Stage Q: smem [j][q], raw copy of packed fp16 pairs ----
    for (int e = tid; e < 1024; e += 256) {
        int j = e >> 5, q4 = (e & 31) * 4;
        *(uint4*)&Qh[j * QST + q4] = *(const uint4*)&qg[j * N_ + q0 + q4];
    }
    __syncthreads();

    // ---- Q A-fragments (k16): 4 ks, 4 regs each ----
    uint32_t qa[4][4];
    #pragma unroll
    for (int ks = 0; ks < 4; ks++) {
        int c = 8 * ks + ti, r = wq + gi;
        qa[ks][0] = Qh[c * QST + r];
        qa[ks][1] = Qh[c * QST + r + 8];
        qa[ks][2] = Qh[(c + 4) * QST + r];
        qa[ks][3] = Qh[(c + 4) * QST + r + 8];
    }
    // Qh read-only hereafter

    float oa[8][4];
    #pragma unroll
    for (int nf = 0; nf < 8; nf++)
        #pragma unroll
        for (int k = 0; k < 4; k++) oa[nf][k] = 0.f;
    float m1 = NEG, m2 = NEG, l1 = 0.f, l2 = 0.f;

    const int r1g = q0 + wq + gi;
    const int mrow = (mbase + r1g * N_) >> 5;

    for (int kc = 0; kc < 16; kc++) {
        asm volatile("cp.async.wait_group 0;" ::: "memory");
        __syncthreads();

        const int widx = mrow + kc * 2;
        uint2 mwa = *(const uint2*)&g_mbits[widx];
        uint2 mwc = *(const uint2*)&g_mbits[widx + 256];

        if (kc + 1 < 16) fill((kc + 1) & 1, kc + 1);

        const uint32_t* Kc = As + ((kc & 1) ? K1_OFF : K0_OFF);
        const uint32_t* Vc = As + ((kc & 1) ? V1_OFF : V0_OFF);

        // ---- S = Q K^T : 32 mma16 ----
        float sa[8][4];
        #pragma unroll
        for (int nf = 0; nf < 8; nf++)
            #pragma unroll
            for (int k = 0; k < 4; k++) sa[nf][k] = 0.f;
        #pragma unroll
        for (int ks = 0; ks < 4; ks++) {
            const uint32_t* kr0 = &Kc[(8 * ks + ti) * KVST + gi];
            const uint32_t* kr1 = &Kc[(8 * ks + ti + 4) * KVST + gi];
            #pragma unroll
            for (int nf = 0; nf < 8; nf++) {
                mma16f(sa[nf], qa[ks], kr0[nf * 8], kr1[nf * 8]);
            }
        }

        // ---- scale + mask ----
        #pragma unroll
        for (int nf = 0; nf < 8; nf++) {
            uint32_t wa = (nf < 4) ? mwa.x : mwa.y;
            uint32_t wc = (nf < 4) ? mwc.x : mwc.y;
            int sh = (nf & 3) * 8 + 2 * ti;
            sa[nf][0] = ((wa >> sh) & 1)       ? NEG : sa[nf][0] * sc2;
            sa[nf][1] = ((wa >> (sh + 1)) & 1) ? NEG : sa[nf][1] * sc2;
            sa[nf][2] = ((wc >> sh) & 1)       ? NEG : sa[nf][2] * sc2;
            sa[nf][3] = ((wc >> (sh + 1)) & 1) ? NEG : sa[nf][3] * sc2;
        }

        // ---- online softmax; P packed straight into fp16 A-frags ----
        float mx1 = NEG, mx2 = NEG;
        #pragma unroll
        for (int nf = 0; nf < 8; nf++) {
            mx1 = fmaxf(mx1, fmaxf(sa[nf][0], sa[nf][1]));
            mx2 = fmaxf(mx2, fmaxf(sa[nf][2], sa[nf][3]));
        }
        mx1 = fmaxf(mx1, __shfl_xor_sync(0xffffffffu, mx1, 1));
        mx1 = fmaxf(mx1, __shfl_xor_sync(0xffffffffu, mx1, 2));
        mx2 = fmaxf(mx2, __shfl_xor_sync(0xffffffffu, mx2, 1));
        mx2 = fmaxf(mx2, __shfl_xor_sync(0xffffffffu, mx2, 2));
        float mn1 = fmaxf(m1, mx1), mn2 = fmaxf(m2, mx2);
        float corr1 = fexp2(m1 - mn1), corr2 = fexp2(m2 - mn2);

        uint32_t pa[4][4];
        float ls1 = 0.f, ls2 = 0.f;
        #pragma unroll
        for (int nf = 0; nf < 8; nf++) {
            float p00 = fexp2(sa[nf][0] - mn1);
            float p01 = fexp2(sa[nf][1] - mn1);
            float p10 = fexp2(sa[nf][2] - mn2);
            float p11 = fexp2(sa[nf][3] - mn2);
            ls1 += p00 + p01;
            ls2 += p10 + p11;
            int kf = nf >> 1;
            if (nf & 1) {
                pa[kf][2] = pack_f16(p00, p01);
                pa[kf][3] = pack_f16(p10, p11);
            } else {
                pa[kf][0] = pack_f16(p00, p01);
                pa[kf][1] = pack_f16(p10, p11);
            }
        }
        ls1 += __shfl_xor_sync(0xffffffffu, ls1, 1);
        ls1 += __shfl_xor_sync(0xffffffffu, ls1, 2);
        ls2 += __shfl_xor_sync(0xffffffffu, ls2, 1);
        ls2 += __shfl_xor_sync(0xffffffffu, ls2, 2);
        l1 = l1 * corr1 + ls1;
        l2 = l2 * corr2 + ls2;
        m1 = mn1; m2 = mn2;
        #pragma unroll
        for (int nf = 0; nf < 8; nf++) {
            oa[nf][0] *= corr1; oa[nf][1] *= corr1;
            oa[nf][2] *= corr2; oa[nf][3] *= corr2;
        }

        // ---- O += P V : 32 mma16, P from registers ----
        #pragma unroll
        for (int kf = 0; kf < 4; kf++) {
            const uint32_t* vr0 = &Vc[(8 * kf + ti) * KVST + gi];
            const uint32_t* vr1 = &Vc[(8 * kf + ti + 4) * KVST + gi];
            #pragma unroll
            for (int nf = 0; nf < 8; nf++) {
                mma16f(oa[nf], pa[kf], vr0[nf * 8], vr1[nf * 8]);
            }
        }
    }
    __syncthreads();

    // ---- normalize + stage to smem [d][q] for coalesced output ----
    float* Od = (float*)(As + K0_OFF);   // overlays buffers
    float il1 = 1.0f / l1, il2 = 1.0f / l2;
    #pragma unroll
    for (int nf = 0; nf < 8; nf++) {
        int d0 = nf * 8 + 2 * ti;
        Od[d0 * 132 + wq + gi]           = oa[nf][0] * il1;
        Od[(d0 + 1) * 132 + wq + gi]     = oa[nf][1] * il1;
        Od[d0 * 132 + wq + gi + 8]       = oa[nf][2] * il2;
        Od[(d0 + 1) * 132 + wq + gi + 8] = oa[nf][3] * il2;
    }
    __syncthreads();

    float* ob = out + (b * C_ + h * D_) * N_;
    for (int e = tid; e < 64 * 32; e += 256) {
        int dd = e >> 5, q4 = (e & 31) * 4;
        *(float4*)&ob[dd * N_ + q0 + q4] = *(const float4*)&Od[dd * 132 + q4];
    }
}

// ---------------------------------------------------------------------------
extern "C" void kernel_launch(void* const* d_in, const int* in_sizes, int n_in,
                              void* d_out, int out_size)
{
    const float* x         = (const float*)d_in[0];
    const float* w_qkv     = (const float*)d_in[1];
    const unsigned char* m = (const unsigned char*)d_in[2];
    float* out             = (float*)d_out;

    cudaFuncSetAttribute(attn_kernel,
                         cudaFuncAttributeMaxDynamicSharedMemorySize, ATTN_SMEM);

    detect_mask_kernel<<<1, 1024>>>((const uint4*)m);
    maskpack_kernel<<<MWORDS / 256, 256>>>(m);
    wsplit_kernel<<<(O3C * C2 + 255) / 256, 256>>>(w_qkv);

    dim3 gemm_grid(N_ / 128, O3C / 128, B_);   // (8, 9, 16)
    qkv_gemm_kernel<<<gemm_grid, 256>>>(x);

    dim3 attn_grid(N_ / 128, HEADS_, B_);      // (8, 6, 16)
    attn_kernel<<<attn_grid, 256, ATTN_SMEM>>>(out);
}

// round 17
// speedup vs baseline: 1.1576x; 1.0094x over previous
#include <cuda_runtime.h>
#include <cuda_bf16.h>
#include <cuda_fp16.h>
#include <math.h>
#include <float.h>
#include <stdint.h>

// Problem constants
#define B_     16
#define C_     384
#define HEADS_ 6
#define D_     64
#define N_     1024
#define O3C    1152
#define C2     (C_ / 2)      // 192

__device__ int g_mask_mode;              // 0 = uint8 bool, 1 = int32, 2 = float32
#define MWORDS (B_ * HEADS_ * N_ * (N_ / 32))
__device__ uint32_t g_mbits[MWORDS];     // bit-packed drop mask

// Pre-split W: fp16 hi/lo k-pairs, [o][c2]
__device__ __align__(16) uint32_t g_wh[O3C * C2];
__device__ __align__(16) uint32_t g_wl[O3C * C2];

// fp16-packed Q/K/V, written directly by the GEMM epilogue.
// Q: g_qh[(bh*32 + j)*1024 + q] = half2(Q[2j][q], Q[2j+1][q])
// K: chunk-major, frag-pair interleaved:
//    g_kh[(bh*16+kc)*2048 + (p*64+m)*2 + s],  j = d-pair index:
//    p = ((j>>3)<<2)|(j&3), s = (j>>2)&1  -> (rows 8ks+ti, 8ks+ti+4) adjacent
// V: same interleave over key-pair index jk within chunk.
#define QKWORDS (B_ * HEADS_ * 32 * 1024)   // 3,145,728
__device__ __align__(16) uint32_t g_qh[QKWORDS];
__device__ __align__(16) uint32_t g_kh[QKWORDS];
__device__ __align__(16) uint32_t g_vh[QKWORDS];

// ---------------------------------------------------------------------------
__device__ __forceinline__ uint32_t pack_f16(float a, float b) {
    __half2 t = __floats2half2_rn(a, b);
    return *(uint32_t*)&t;
}

// fp16 m16n8k16 row.col mma, f32 acc in-place
__device__ __forceinline__ void mma16f(float* c, const uint32_t* a,
                                       uint32_t b0, uint32_t b1) {
    asm volatile(
        "mma.sync.aligned.m16n8k16.row.col.f32.f16.f16.f32 "
        "{%0,%1,%2,%3}, {%4,%5,%6,%7}, {%8,%9}, {%0,%1,%2,%3};\n"
        : "+f"(c[0]), "+f"(c[1]), "+f"(c[2]), "+f"(c[3])
        : "r"(a[0]), "r"(a[1]), "r"(a[2]), "r"(a[3]), "r"(b0), "r"(b1));
}

__device__ __forceinline__ void cpa16(void* smem, const void* g) {
    uint32_t s = (uint32_t)__cvta_generic_to_shared(smem);
    asm volatile("cp.async.cg.shared.global [%0], [%1], 16;" :: "r"(s), "l"(g));
}

__device__ __forceinline__ float fexp2(float y) {
    y = fmaxf(y, -126.0f);
    float z = y + 12582912.0f;
    int   n = __float_as_int(z) - 0x4B400000;
    float f = y - (z - 12582912.0f);
    float p = 1.3333558146e-3f;
    p = fmaf(p, f, 9.6181291076e-3f);
    p = fmaf(p, f, 5.5504108665e-2f);
    p = fmaf(p, f, 2.4022650696e-1f);
    p = fmaf(p, f, 6.9314718056e-1f);
    p = fmaf(p, f, 1.0f);
    return __int_as_float(__float_as_int(p) + (n << 23));
}

// ---------------------------------------------------------------------------
__global__ void detect_mask_kernel(const uint4* __restrict__ m) {
    __shared__ int s_off4, s_gt1;
    if (threadIdx.x == 0) { s_off4 = 0; s_gt1 = 0; }
    __syncthreads();
    int off4 = 0, gt1 = 0;
    for (int i = threadIdx.x; i < 4096; i += blockDim.x) {
        uint4 v = m[i];
        unsigned a = v.x | v.y | v.z | v.w;
        if (a & 0xFFFFFF00u) off4 = 1;
        if (a & 0xFEFEFEFEu) gt1  = 1;
    }
    if (off4) atomicOr(&s_off4, 1);
    if (gt1)  atomicOr(&s_gt1, 1);
    __syncthreads();
    if (threadIdx.x == 0) g_mask_mode = s_gt1 ? 2 : (s_off4 ? 0 : 1);
}

// ---------------------------------------------------------------------------
#define B4(t) (((t) | ((t) >> 7) | ((t) >> 14) | ((t) >> 21)) & 0xFu)

__global__ void maskpack_kernel(const unsigned char* __restrict__ m) {
    int w = blockIdx.x * blockDim.x + threadIdx.x;
    if (w >= MWORDS) return;
    int mode = g_mask_mode;
    uint32_t bits = 0;
    if (mode == 0) {
        const uint4* p = (const uint4*)m + w * 2;
        uint4 a = p[0], b = p[1];
        bits  = B4(a.x) | (B4(a.y) << 4) | (B4(a.z) << 8)  | (B4(a.w) << 12)
              | (B4(b.x) << 16) | (B4(b.y) << 20) | (B4(b.z) << 24) | (B4(b.w) << 28);
    } else if (mode == 1) {
        const int4* p = (const int4*)m + w * 8;
        #pragma unroll
        for (int i = 0; i < 8; i++) {
            int4 v = p[i];
            bits |= (uint32_t)((v.x != 0) | ((v.y != 0) << 1) |
                               ((v.z != 0) << 2) | ((v.w != 0) << 3)) << (i * 4);
        }
    } else {
        const float4* p = (const float4*)m + w * 8;
        #pragma unroll
        for (int i = 0; i < 8; i++) {
            float4 v = p[i];
            bits |= (uint32_t)((v.x != 0.f) | ((v.y != 0.f) << 1) |
                               ((v.z != 0.f) << 2) | ((v.w != 0.f) << 3)) << (i * 4);
        }
    }
    g_mbits[w] = bits;
}

// ---------------------------------------------------------------------------
// W split (fp16 hi/lo, horizontal k-pairs)
// ---------------------------------------------------------------------------
__global__ void wsplit_kernel(const float* __restrict__ w) {
    int idx = blockIdx.x * blockDim.x + threadIdx.x;
    if (idx >= O3C * C2) return;
    float2 v = *(const float2*)&w[idx * 2];
    __half h0 = __float2half_rn(v.x);
    __half h1 = __float2half_rn(v.y);
    __half2 hp; hp.x = h0; hp.y = h1;
    g_wh[idx] = *(uint32_t*)&hp;
    g_wl[idx] = pack_f16(v.x - __half2float(h0),
                         v.y - __half2float(h1));
}

// ---------------------------------------------------------------------------
// QKV GEMM: fp16, W hi/lo 2-term, X single fp16. Register-prefetched chunks.
// Epilogue packs straight to fp16 Q (q-major) and interleaved K/V chunks.
// Tile 128(o) x 128(n), KC=16. 8 warps, warp 32x64. grid (8, 9, 16)
// ---------------------------------------------------------------------------
#define WPST 12
#define XPST 136
#define NCHUNK (C_ / 16)

__global__ __launch_bounds__(256, 2) void qkv_gemm_kernel(
    const float* __restrict__ x)
{
    __shared__ uint32_t Whp[128 * WPST], Wlp[128 * WPST];
    __shared__ uint32_t Xhp[8 * XPST];

    const int b  = blockIdx.z;
    const int o0 = blockIdx.y * 128;
    const int n0 = blockIdx.x * 128;
    const int tid  = threadIdx.x;
    const int wid  = tid >> 5;
    const int lane = tid & 31;
    const int m_base = (wid >> 1) * 32;
    const int n_base = (wid & 1) * 64;
    const int gi = lane >> 2;
    const int ti = lane & 3;

    const float* xb = x + b * C_ * N_;

    const int wo  = tid >> 1;
    const int wk2 = (tid & 1) * 4;
    const int xc2 = tid >> 5;
    const int xn  = (tid & 31) * 4;

    float acc[2][8][4];
    #pragma unroll
    for (int mf = 0; mf < 2; mf++)
        #pragma unroll
        for (int nf = 0; nf < 8; nf++)
            #pragma unroll
            for (int k = 0; k < 4; k++) acc[mf][nf][k] = 0.f;

    const uint32_t* wh_p = &g_wh[(o0 + wo) * C2 + wk2];
    const uint32_t* wl_p = &g_wl[(o0 + wo) * C2 + wk2];
    const float*    x_p  = &xb[(2 * xc2) * N_ + n0 + xn];
    uint4  whv = *(const uint4*)wh_p;
    uint4  wlv = *(const uint4*)wl_p;
    float4 xr0 = *(const float4*)x_p;
    float4 xr1 = *(const float4*)(x_p + N_);

    for (int ci = 0; ci < NCHUNK; ci++) {
        *(uint4*)&Whp[wo * WPST + wk2] = whv;
        *(uint4*)&Wlp[wo * WPST + wk2] = wlv;
        {
            uint4 hv;
            hv.x = pack_f16(xr0.x, xr1.x);
            hv.y = pack_f16(xr0.y, xr1.y);
            hv.z = pack_f16(xr0.z, xr1.z);
            hv.w = pack_f16(xr0.w, xr1.w);
            *(uint4*)&Xhp[xc2 * XPST + xn] = hv;
        }
        __syncthreads();

        if (ci + 1 < NCHUNK) {
            wh_p += 8; wl_p += 8; x_p += 16 * N_;
            whv = *(const uint4*)wh_p;
            wlv = *(const uint4*)wl_p;
            xr0 = *(const float4*)x_p;
            xr1 = *(const float4*)(x_p + N_);
        }

        uint32_t ah[2][4], al[2][4];
        #pragma unroll
        for (int mf = 0; mf < 2; mf++) {
            int r = m_base + mf * 16 + gi;
            ah[mf][0] = Whp[r * WPST + ti];
            ah[mf][1] = Whp[(r + 8) * WPST + ti];
            ah[mf][2] = Whp[r * WPST + ti + 4];
            ah[mf][3] = Whp[(r + 8) * WPST + ti + 4];
            al[mf][0] = Wlp[r * WPST + ti];
            al[mf][1] = Wlp[(r + 8) * WPST + ti];
            al[mf][2] = Wlp[r * WPST + ti + 4];
            al[mf][3] = Wlp[(r + 8) * WPST + ti + 4];
        }
        #pragma unroll
        for (int nf = 0; nf < 8; nf++) {
            int col = n_base + nf * 8 + gi;
            uint32_t bh0 = Xhp[ti * XPST + col];
            uint32_t bh1 = Xhp[(ti + 4) * XPST + col];
            #pragma unroll
            for (int mf = 0; mf < 2; mf++) {
                mma16f(acc[mf][nf], ah[mf], bh0, bh1);
                mma16f(acc[mf][nf], al[mf], bh0, bh1);
            }
        }
        __syncthreads();
    }

    // ---- Epilogue: pack straight to fp16 Q/K/V ----
    const int type  = o0 / C_;        // 0=Q, 1=K, 2=V
    const int obase = o0 - type * C_;

    if (type == 0) {
        // Q: q-major, half2 pairs over adjacent d-rows (shfl with gi+4 lane)
        #pragma unroll
        for (int mf = 0; mf < 2; mf++) {
            int r0 = obase + m_base + mf * 16 + gi;
            int bh = b * HEADS_ + (r0 >> 6);
            int d0 = r0 & 63;
            #pragma unroll
            for (int nf = 0; nf < 8; nf++) {
                int q = n0 + n_base + nf * 8 + 2 * ti;
                float a0 = acc[mf][nf][0], a1 = acc[mf][nf][1];
                float c0 = acc[mf][nf][2], c1 = acc[mf][nf][3];
                float b0v = __shfl_down_sync(0xffffffffu, a0, 4);
                float b1v = __shfl_down_sync(0xffffffffu, a1, 4);
                float e0v = __shfl_down_sync(0xffffffffu, c0, 4);
                float e1v = __shfl_down_sync(0xffffffffu, c1, 4);
                if ((gi & 1) == 0) {
                    int j0 = d0 >> 1;
                    int j1 = (d0 + 8) >> 1;
                    *(uint2*)&g_qh[(bh * 32 + j0) * N_ + q] =
                        make_uint2(pack_f16(a0, b0v), pack_f16(a1, b1v));
                    *(uint2*)&g_qh[(bh * 32 + j1) * N_ + q] =
                        make_uint2(pack_f16(c0, e0v), pack_f16(c1, e1v));
                }
            }
        }
    } else if (type == 1) {
        // K: chunk-major interleaved pair layout
        #pragma unroll
        for (int mf = 0; mf < 2; mf++) {
            int r0 = obase + m_base + mf * 16 + gi;
            int bh = b * HEADS_ + (r0 >> 6);
            int d0 = r0 & 63;
            #pragma unroll
            for (int nf = 0; nf < 8; nf++) {
                int q = n0 + n_base + nf * 8 + 2 * ti;
                float a0 = acc[mf][nf][0], a1 = acc[mf][nf][1];
                float c0 = acc[mf][nf][2], c1 = acc[mf][nf][3];
                float b0v = __shfl_down_sync(0xffffffffu, a0, 4);
                float b1v = __shfl_down_sync(0xffffffffu, a1, 4);
                float e0v = __shfl_down_sync(0xffffffffu, c0, 4);
                float e1v = __shfl_down_sync(0xffffffffu, c1, 4);
                if ((gi & 1) == 0) {
                    int j0 = d0 >> 1;
                    int j1 = (d0 + 8) >> 1;
                    int p0 = ((j0 >> 3) << 2) | (j0 & 3), s0 = (j0 >> 2) & 1;
                    int p1 = ((j1 >> 3) << 2) | (j1 & 3), s1 = (j1 >> 2) & 1;
                    int kc = q >> 6, mm = q & 63;
                    uint32_t* base = g_kh + (bh * 16 + kc) * 2048;
                    base[(p0 * 64 + mm) * 2 + s0]     = pack_f16(a0, b0v);
                    base[(p0 * 64 + mm + 1) * 2 + s0] = pack_f16(a1, b1v);
                    base[(p1 * 64 + mm) * 2 + s1]     = pack_f16(c0, e0v);
                    base[(p1 * 64 + mm + 1) * 2 + s1] = pack_f16(c1, e1v);
                }
            }
        }
    } else {
        // V: chunk-major interleaved pair layout over key-pairs (in-thread)
        #pragma unroll
        for (int mf = 0; mf < 2; mf++) {
            int r0 = obase + m_base + mf * 16 + gi;
            int bh = b * HEADS_ + (r0 >> 6);
            int d0 = r0 & 63;
            #pragma unroll
            for (int nf = 0; nf < 8; nf++) {
                int q = n0 + n_base + nf * 8 + 2 * ti;
                int jk = q >> 1;
                int kc = jk >> 5, jl = jk & 31;
                int pv = ((jl >> 3) << 2) | (jl & 3), s = (jl >> 2) & 1;
                uint32_t* base = g_vh + (bh * 16 + kc) * 2048;
                base[(pv * 64 + d0) * 2 + s]     = pack_f16(acc[mf][nf][0], acc[mf][nf][1]);
                base[(pv * 64 + d0 + 8) * 2 + s] = pack_f16(acc[mf][nf][2], acc[mf][nf][3]);
            }
        }
    }
}

// ---------------------------------------------------------------------------
// Fused flash attention: fp16 mma, interleaved K/V -> LDS.64 B-frags.
// 128 q rows, 8 warps. Double-buffered cp.async K/V. grid = (8, 6, 16)
// ---------------------------------------------------------------------------
#define QST 132
#define KVST2 68                           // uint2 row stride (64 data + 4 pad)
#define QH_WORDS (32 * QST)                // 4224
#define KVBUF_WORDS (16 * KVST2 * 2)       // 2176
#define K0_OFF QH_WORDS                    // 4224
#define V0_OFF (K0_OFF + KVBUF_WORDS)      // 6400
#define K1_OFF (V0_OFF + KVBUF_WORDS)      // 8576
#define V1_OFF (K1_OFF + KVBUF_WORDS)      // 10752
#define SMEM_WORDS (V1_OFF + KVBUF_WORDS)  // 12928
#define ATTN_SMEM (SMEM_WORDS * 4)         // 51712 B

__global__ __launch_bounds__(256, 2) void attn_kernel(float* __restrict__ out)
{
    extern __shared__ uint32_t As[];
    uint32_t* Qh = As;                    // [32 j][QST] fp16x2 Q pairs

    const int q0 = blockIdx.x * 128;
    const int h  = blockIdx.y;
    const int b  = blockIdx.z;
    const int tid  = threadIdx.x;
    const int wid  = tid >> 5;
    const int lane = tid & 31;
    const int gi = lane >> 2;
    const int ti = lane & 3;
    const int wq = wid * 16;

    const float sc2 = rsqrtf((float)C_) * 1.4426950408889634f;
    const float NEG = -1e30f;

    const int bh = b * HEADS_ + h;
    const uint32_t* qg = g_qh + bh * 32 * N_;
    const int mbase = bh * N_ * N_;

    auto fill = [&](int sel, int kc) {
        uint2* Kb = (uint2*)(As + (sel ? K1_OFF : K0_OFF));
        uint2* Vb = (uint2*)(As + (sel ? V1_OFF : V0_OFF));
        const uint2* kg = (const uint2*)(g_kh + (bh * 16 + kc) * 2048);
        const uint2* vg = (const uint2*)(g_vh + (bh * 16 + kc) * 2048);
        #pragma unroll
        for (int i = 0; i < 2; i++) {
            int e = tid + i * 256;           // 0..511
            int p = e >> 5, m2 = (e & 31) * 2;
            cpa16(&Kb[p * KVST2 + m2], &kg[p * 64 + m2]);
            cpa16(&Vb[p * KVST2 + m2], &vg[p * 64 + m2]);
        }
        asm volatile("cp.async.commit_group;" ::: "memory");
    };

    fill(0, 0);

    // ---- Stage Q: smem [j][q], raw copy of packed fp16 pairs ----
    for (int e = tid; e < 1024; e += 256) {
        int j = e >> 5, q4 = (e & 31) * 4;
        *(uint4*)&Qh[j * QST + q4] = *(const uint4*)&qg[j * N_ + q0 + q4];
    }
    __syncthreads();

    // ---- Q A-fragments (k16): 4 ks, 4 regs each ----
    uint32_t qa[4][4];
    #pragma unroll
    for (int ks = 0; ks < 4; ks++) {
        int c = 8 * ks + ti, r = wq + gi;
        qa[ks][0] = Qh[c * QST + r];
        qa[ks][1] = Qh[c * QST + r + 8];
        qa[ks][2] = Qh[(c + 4) * QST + r];
        qa[ks][3] = Qh[(c + 4) * QST + r + 8];
    }
    // Qh read-only hereafter

    float oa[8][4];
    #pragma unroll
    for (int nf = 0; nf < 8; nf++)
        #pragma unroll
        for (int k = 0; k < 4; k++) oa[nf][k] = 0.f;
    float m1 = NEG, m2 = NEG, l1 = 0.f, l2 = 0.f;

    const int r1g = q0 + wq + gi;
    const int mrow = (mbase + r1g * N_) >> 5;

    for (int kc = 0; kc < 16; kc++) {
        asm volatile("cp.async.wait_group 0;" ::: "memory");
        __syncthreads();

        const int widx = mrow + kc * 2;
        uint2 mwa = *(const uint2*)&g_mbits[widx];
        uint2 mwc = *(const uint2*)&g_mbits[widx + 256];

        if (kc + 1 < 16) fill((kc + 1) & 1, kc + 1);

        const uint2* Kc2 = (const uint2*)(As + ((kc & 1) ? K1_OFF : K0_OFF));
        const uint2* Vc2 = (const uint2*)(As + ((kc & 1) ? V1_OFF : V0_OFF));

        // ---- S = Q K^T : 32 mma16, B-frags one LDS.64 each ----
        float sa[8][4];
        #pragma unroll
        for (int nf = 0; nf < 8; nf++)
            #pragma unroll
            for (int k = 0; k < 4; k++) sa[nf][k] = 0.f;
        #pragma unroll
        for (int ks = 0; ks < 4; ks++) {
            const uint2* kr = &Kc2[(ks * 4 + ti) * KVST2 + gi];
            #pragma unroll
            for (int nf = 0; nf < 8; nf++) {
                uint2 bb = kr[nf * 8];
                mma16f(sa[nf], qa[ks], bb.x, bb.y);
            }
        }

        // ---- scale + mask ----
        #pragma unroll
        for (int nf = 0; nf < 8; nf++) {
            uint32_t wa = (nf < 4) ? mwa.x : mwa.y;
            uint32_t wc = (nf < 4) ? mwc.x : mwc.y;
            int sh = (nf & 3) * 8 + 2 * ti;
            sa[nf][0] = ((wa >> sh) & 1)       ? NEG : sa[nf][0] * sc2;
            sa[nf][1] = ((wa >> (sh + 1)) & 1) ? NEG : sa[nf][1] * sc2;
            sa[nf][2] = ((wc >> sh) & 1)       ? NEG : sa[nf][2] * sc2;
            sa[nf][3] = ((wc >> (sh + 1)) & 1) ? NEG : sa[nf][3] * sc2;
        }

        // ---- online softmax; P packed straight into fp16 A-frags ----
        float mx1 = NEG, mx2 = NEG;
        #pragma unroll
        for (int nf = 0; nf < 8; nf++) {
            mx1 = fmaxf(mx1, fmaxf(sa[nf][0], sa[nf][1]));
            mx2 = fmaxf(mx2, fmaxf(sa[nf][2], sa[nf][3]));
        }
        mx1 = fmaxf(mx1, __shfl_xor_sync(0xffffffffu, mx1, 1));
        mx1 = fmaxf(mx1, __shfl_xor_sync(0xffffffffu, mx1, 2));
        mx2 = fmaxf(mx2, __shfl_xor_sync(0xffffffffu, mx2, 1));
        mx2 = fmaxf(mx2, __shfl_xor_sync(0xffffffffu, mx2, 2));
        float mn1 = fmaxf(m1, mx1), mn2 = fmaxf(m2, mx2);
        float corr1 = fexp2(m1 - mn1), corr2 = fexp2(m2 - mn2);

        uint32_t pa[4][4];
        float ls1 = 0.f, ls2 = 0.f;
        #pragma unroll
        for (int nf = 0; nf < 8; nf++) {
            float p00 = fexp2(sa[nf][0] - mn1);
            float p01 = fexp2(sa[nf][1] - mn1);
            float p10 = fexp2(sa[nf][2] - mn2);
            float p11 = fexp2(sa[nf][3] - mn2);
            ls1 += p00 + p01;
            ls2 += p10 + p11;
            int kf = nf >> 1;
            if (nf & 1) {
                pa[kf][2] = pack_f16(p00, p01);
                pa[kf][3] = pack_f16(p10, p11);
            } else {
                pa[kf][0] = pack_f16(p00, p01);
                pa[kf][1] = pack_f16(p10, p11);
            }
        }
        ls1 += __shfl_xor_sync(0xffffffffu, ls1, 1);
        ls1 += __shfl_xor_sync(0xffffffffu, ls1, 2);
        ls2 += __shfl_xor_sync(0xffffffffu, ls2, 1);
        ls2 += __shfl_xor_sync(0xffffffffu, ls2, 2);
        l1 = l1 * corr1 + ls1;
        l2 = l2 * corr2 + ls2;
        m1 = mn1; m2 = mn2;
        #pragma unroll
        for (int nf = 0; nf < 8; nf++) {
            oa[nf][0] *= corr1; oa[nf][1] *= corr1;
            oa[nf][2] *= corr2; oa[nf][3] *= corr2;
        }

        // ---- O += P V : 32 mma16, B-frags one LDS.64 each ----
        #pragma unroll
        for (int kf = 0; kf < 4; kf++) {
            const uint2* vr = &Vc2[(kf * 4 + ti) * KVST2 + gi];
            #pragma unroll
            for (int nf = 0; nf < 8; nf++) {
                uint2 vv = vr[nf * 8];
                mma16f(oa[nf], pa[kf], vv.x, vv.y);
            }
        }
    }
    __syncthreads();

    // ---- normalize + stage to smem [d][q] for coalesced output ----
    float* Od = (float*)(As + K0_OFF);   // overlays buffers (8448 <= 8704 words)
    float il1 = 1.0f / l1, il2 = 1.0f / l2;
    #pragma unroll
    for (int nf = 0; nf < 8; nf++) {
        int d0 = nf * 8 + 2 * ti;
        Od[d0 * 132 + wq + gi]           = oa[nf][0] * il1;
        Od[(d0 + 1) * 132 + wq + gi]     = oa[nf][1] * il1;
        Od[d0 * 132 + wq + gi + 8]       = oa[nf][2] * il2;
        Od[(d0 + 1) * 132 + wq + gi + 8] = oa[nf][3] * il2;
    }
    __syncthreads();

    float* ob = out + (b * C_ + h * D_) * N_;
    for (int e = tid; e < 64 * 32; e += 256) {
        int dd = e >> 5, q4 = (e & 31) * 4;
        *(float4*)&ob[dd * N_ + q0 + q4] = *(const float4*)&Od[dd * 132 + q4];
    }
}

// ---------------------------------------------------------------------------
extern "C" void kernel_launch(void* const* d_in, const int* in_sizes, int n_in,
                              void* d_out, int out_size)
{
    const float* x         = (const float*)d_in[0];
    const float* w_qkv     = (const float*)d_in[1];
    const unsigned char* m = (const unsigned char*)d_in[2];
    float* out             = (float*)d_out;

    cudaFuncSetAttribute(attn_kernel,
                         cudaFuncAttributeMaxDynamicSharedMemorySize, ATTN_SMEM);

    detect_mask_kernel<<<1, 1024>>>((const uint4*)m);
    maskpack_kernel<<<MWORDS / 256, 256>>>(m);
    wsplit_kernel<<<(O3C * C2 + 255) / 256, 256>>>(w_qkv);

    dim3 gemm_grid(N_ / 128, O3C / 128, B_);   // (8, 9, 16)
    qkv_gemm_kernel<<<gemm_grid, 256>>>(x);

    dim3 attn_grid(N_ / 128, HEADS_, B_);      // (8, 6, 16)
    attn_kernel<<<attn_grid, 256, ATTN_SMEM>>>(out);
}